// round 13
// baseline (speedup 1.0000x reference)
#include <cuda_runtime.h>
#include <cuda_bf16.h>
#include <math.h>
#include <stdint.h>

// Problem constants
#define B_ 4
#define T_ 2048
#define C_ 2048
#define H_ 16
#define DH 128
#define THREE_C (3 * C_)
#define M_ (B_ * T_)   // 8192

// ---------------------------------------------------------------------------
// Device-global scratch (allocation-free)
// ---------------------------------------------------------------------------
__device__ __nv_bfloat16 g_xc_h[(size_t)M_ * C_];
__device__ __nv_bfloat16 g_xc_l[(size_t)M_ * C_];
__device__ __nv_bfloat16 g_yc_h[(size_t)M_ * C_];
__device__ __nv_bfloat16 g_yc_l[(size_t)M_ * C_];
__device__ __nv_bfloat16 g_wq_h[(size_t)THREE_C * C_];      // w_qkv^T [6144,2048]
__device__ __nv_bfloat16 g_wq_l[(size_t)THREE_C * C_];
__device__ __nv_bfloat16 g_wp_h[(size_t)C_ * C_];           // w_proj^T [2048,2048]
__device__ __nv_bfloat16 g_wp_l[(size_t)C_ * C_];
// Roped/scaled bf16 hi/lo Q,K and split V, layout [M_][C_] (c = h*128+d)
__device__ __nv_bfloat16 g_qh[(size_t)M_ * C_];
__device__ __nv_bfloat16 g_ql[(size_t)M_ * C_];
__device__ __nv_bfloat16 g_kh[(size_t)M_ * C_];
__device__ __nv_bfloat16 g_kl[(size_t)M_ * C_];
__device__ __nv_bfloat16 g_vh[(size_t)M_ * C_];
__device__ __nv_bfloat16 g_vl[(size_t)M_ * C_];

// ---------------------------------------------------------------------------
// Helpers
// ---------------------------------------------------------------------------
__device__ __forceinline__ uint32_t smem_u32(const void* p) {
    uint32_t a;
    asm("{ .reg .u64 t; cvta.to.shared.u64 t, %1; cvt.u32.u64 %0, t; }"
        : "=r"(a) : "l"(p));
    return a;
}
static __device__ __forceinline__ uint32_t sw128(uint32_t x) {
    return x ^ ((x >> 3) & 0x70);
}
__device__ __forceinline__ void cpa16(uint32_t s, const void* g) {
    asm volatile("cp.async.cg.shared.global [%0], [%1], 16;" :: "r"(s), "l"(g));
}
#define CP_COMMIT() asm volatile("cp.async.commit_group;" ::: "memory")
#define CP_WAIT1()  asm volatile("cp.async.wait_group 1;" ::: "memory")
#define CP_WAIT0()  asm volatile("cp.async.wait_group 0;" ::: "memory")

__device__ __forceinline__ void ldm4(uint32_t* r, uint32_t addr) {
    asm volatile("ldmatrix.sync.aligned.m8n8.x4.shared.b16 {%0,%1,%2,%3}, [%4];"
                 : "=r"(r[0]), "=r"(r[1]), "=r"(r[2]), "=r"(r[3]) : "r"(addr));
}
__device__ __forceinline__ void ldm4t(uint32_t* r, uint32_t addr) {
    asm volatile("ldmatrix.sync.aligned.m8n8.x4.trans.shared.b16 {%0,%1,%2,%3}, [%4];"
                 : "=r"(r[0]), "=r"(r[1]), "=r"(r[2]), "=r"(r[3]) : "r"(addr));
}
__device__ __forceinline__ void mma16816(float* d, const uint32_t* a,
                                         uint32_t b0, uint32_t b1) {
    asm volatile(
        "mma.sync.aligned.m16n8k16.row.col.f32.bf16.bf16.f32 "
        "{%0,%1,%2,%3}, {%4,%5,%6,%7}, {%8,%9}, {%0,%1,%2,%3};"
        : "+f"(d[0]), "+f"(d[1]), "+f"(d[2]), "+f"(d[3])
        : "r"(a[0]), "r"(a[1]), "r"(a[2]), "r"(a[3]), "r"(b0), "r"(b1));
}
__device__ __forceinline__ uint32_t packbf(float a, float b) {
    __nv_bfloat162 t = __floats2bfloat162_rn(a, b);   // .x = a (low 16 bits)
    return *(uint32_t*)&t;
}
__device__ __forceinline__ float ex2f(float x) {
    float r;
    asm("ex2.approx.f32 %0, %1;" : "=f"(r) : "f"(x));
    return r;
}

// ---------------------------------------------------------------------------
// Elementwise fp32 -> bf16 (hi, lo) split. n8 = elements/8.
// ---------------------------------------------------------------------------
__global__ void convert_hilo(const float* __restrict__ X,
                             __nv_bfloat16* __restrict__ Hh,
                             __nv_bfloat16* __restrict__ Hl, long n8)
{
    long i = (long)blockIdx.x * blockDim.x + threadIdx.x;
    if (i >= n8) return;
    float4 a = ((const float4*)X)[i * 2 + 0];
    float4 b = ((const float4*)X)[i * 2 + 1];
    float v[8] = {a.x, a.y, a.z, a.w, b.x, b.y, b.z, b.w};
    union { __nv_bfloat16 e[8]; uint4 u; } ph, pl;
#pragma unroll
    for (int j = 0; j < 8; j++) {
        __nv_bfloat16 h = __float2bfloat16(v[j]);
        ph.e[j] = h;
        pl.e[j] = __float2bfloat16(v[j] - __bfloat162float(h));
    }
    ((uint4*)Hh)[i] = ph.u;
    ((uint4*)Hl)[i] = pl.u;
}

// ---------------------------------------------------------------------------
// Transpose + split: W[K,N] fp32 row-major -> Th/Tl [N,K] bf16 row-major
// ---------------------------------------------------------------------------
__global__ void wconv(const float* __restrict__ W, __nv_bfloat16* __restrict__ Th,
                      __nv_bfloat16* __restrict__ Tl, int K, int N)
{
    __shared__ float ts[32][33];
    int n0 = blockIdx.x * 32, k0 = blockIdx.y * 32;
    int tx = threadIdx.x, ty = threadIdx.y;
    for (int i = ty; i < 32; i += 8)
        ts[i][tx] = W[(size_t)(k0 + i) * N + n0 + tx];
    __syncthreads();
    for (int i = ty; i < 32; i += 8) {
        float v = ts[tx][i];
        __nv_bfloat16 h = __float2bfloat16(v);
        __nv_bfloat16 l = __float2bfloat16(v - __bfloat162float(h));
        size_t o = (size_t)(n0 + i) * K + k0 + tx;
        Th[o] = h;
        Tl[o] = l;
    }
}

// ---------------------------------------------------------------------------
// GEMM v2 config: CTA 128x256, warp tile 64x64 (2x4 warp grid), BK=64,
// 2-stage cp.async double buffer. MMA:ldsm = 6 (vs 4 before).
// Stage: A_H 16KB | A_L 16KB | B_H 32KB | B_L 32KB = 96KB; 2 stages = 192KB.
// ---------------------------------------------------------------------------
#define GEMM_THREADS 256
#define BKc 64
#define G2_AH 0
#define G2_AL 16384
#define G2_BH 32768
#define G2_BL 65536
#define G2_STG 98304
#define G2_DSM (2 * G2_STG + 1024)

// Shared mainloop emitted in both kernels (copy, no templates).
#define G2_MAINLOOP(K_)                                                        \
    const int nch = (K_) / BKc;                                                \
    auto load_stage = [&](int st, int k0) {                                    \
        uint32_t sbase = sb + st * G2_STG;                                     \
        _Pragma("unroll")                                                      \
        for (int rep = 0; rep < 4; rep++) {                                    \
            int i = tid + rep * GEMM_THREADS;                                  \
            int row = i >> 3, cc = i & 7;                                      \
            uint32_t so = sw128((uint32_t)(row * 128 + cc * 16));              \
            size_t ga = (size_t)(rowBase + row) * (K_) + k0 + cc * 8;          \
            cpa16(sbase + G2_AH + so, Ah + ga);                                \
            cpa16(sbase + G2_AL + so, Al + ga);                                \
        }                                                                      \
        _Pragma("unroll")                                                      \
        for (int rep = 0; rep < 8; rep++) {                                    \
            int i = tid + rep * GEMM_THREADS;                                  \
            int row = i >> 3, cc = i & 7;                                      \
            uint32_t so = sw128((uint32_t)(row * 128 + cc * 16));              \
            size_t gb = (size_t)(colBase + row) * (K_) + k0 + cc * 8;          \
            cpa16(sbase + G2_BH + so, Bh + gb);                                \
            cpa16(sbase + G2_BL + so, Bl + gb);                                \
        }                                                                      \
    };                                                                         \
    load_stage(0, 0); CP_COMMIT();                                             \
    float acc[4][8][4];                                                        \
    _Pragma("unroll")                                                          \
    for (int mi = 0; mi < 4; mi++)                                             \
        _Pragma("unroll")                                                      \
        for (int ni = 0; ni < 8; ni++)                                         \
            _Pragma("unroll")                                                  \
            for (int e = 0; e < 4; e++) acc[mi][ni][e] = 0.f;                  \
    const int lrow = lane & 15;                                                \
    const int lchunk = (lane >> 4) * 16;                                       \
    for (int c = 0; c < nch; c++) {                                            \
        if (c + 1 < nch) {                                                     \
            load_stage((c + 1) & 1, (c + 1) * BKc); CP_COMMIT(); CP_WAIT1();   \
        } else { CP_WAIT0(); }                                                 \
        __syncthreads();                                                       \
        const uint32_t sbase = sb + (c & 1) * G2_STG;                          \
        _Pragma("unroll")                                                      \
        for (int ks = 0; ks < 4; ks++) {                                       \
            const int kb = ks * 32 + lchunk;                                   \
            uint32_t bh[4][4], bl[4][4];                                       \
            _Pragma("unroll")                                                  \
            for (int g = 0; g < 4; g++) {                                      \
                uint32_t bo = sw128((uint32_t)((wn + g * 16 + lrow) * 128 + kb)); \
                ldm4(bh[g], sbase + G2_BH + bo);                               \
                ldm4(bl[g], sbase + G2_BL + bo);                               \
            }                                                                  \
            _Pragma("unroll")                                                  \
            for (int mi = 0; mi < 4; mi++) {                                   \
                uint32_t ah[4], al[4];                                         \
                uint32_t ao = sw128((uint32_t)((wm + mi * 16 + lrow) * 128 + kb)); \
                ldm4(ah, sbase + G2_AH + ao);                                  \
                ldm4(al, sbase + G2_AL + ao);                                  \
                _Pragma("unroll")                                              \
                for (int ni = 0; ni < 8; ni++) {                               \
                    int g = ni >> 1, hf = ni & 1;                              \
                    mma16816(acc[mi][ni], ah, bh[g][hf], bh[g][hf + 2]);       \
                    mma16816(acc[mi][ni], ah, bl[g][hf], bl[g][hf + 2]);       \
                    mma16816(acc[mi][ni], al, bh[g][hf], bh[g][hf + 2]);       \
                }                                                              \
            }                                                                  \
        }                                                                      \
        __syncthreads();                                                       \
    }

// ---------------------------------------------------------------------------
// GEMM #1: out = x @ w_qkv + b_qkv, epilogue RoPE + q scale + bf16 hi/lo split
// ---------------------------------------------------------------------------
__global__ __launch_bounds__(GEMM_THREADS, 1)
void gemm_qkv_rope(const __nv_bfloat16* __restrict__ Ah,
                   const __nv_bfloat16* __restrict__ Al,
                   const __nv_bfloat16* __restrict__ Bh,
                   const __nv_bfloat16* __restrict__ Bl,
                   const float* __restrict__ bias,
                   __nv_bfloat16* __restrict__ qh, __nv_bfloat16* __restrict__ ql,
                   __nv_bfloat16* __restrict__ kh, __nv_bfloat16* __restrict__ kl,
                   __nv_bfloat16* __restrict__ vh, __nv_bfloat16* __restrict__ vl)
{
    extern __shared__ char dsm[];
    const uint32_t raw = smem_u32(dsm);
    const uint32_t sb = (raw + 1023u) & ~1023u;

    const int tid = threadIdx.x;
    const int wid = tid >> 5, lane = tid & 31;
    const int wm = (wid & 1) * 64;        // 2 m-warps
    const int wn = (wid >> 1) * 64;       // 4 n-warps
    const int rowBase = blockIdx.y * 128;
    const int colBase = blockIdx.x * 256;

    G2_MAINLOOP(C_)

    // Epilogue: bias, RoPE on q/k pairs, q scale (1/sqrt(dh))*log2e, split hi/lo
    const float QSC = 0.08838834764831845f * 1.4426950408889634f;
    const int gro = lane >> 2, thr = lane & 3;
#pragma unroll
    for (int mi = 0; mi < 4; mi++) {
        int r0 = rowBase + wm + mi * 16 + gro;
        int t0 = r0 & (T_ - 1), t1 = (r0 + 8) & (T_ - 1);
#pragma unroll
        for (int ni = 0; ni < 8; ni++) {
            int cb = colBase + wn + ni * 8 + thr * 2;   // even
            int sel = cb >> 11;          // 0=q, 1=k, 2=v
            int jj = cb & 2047;
            float bx = bias[cb], by = bias[cb + 1];
            float v00 = acc[mi][ni][0] + bx, v01 = acc[mi][ni][1] + by;
            float v10 = acc[mi][ni][2] + bx, v11 = acc[mi][ni][3] + by;
            if (sel < 2) {
                float e = (float)jj * (1.0f / (float)C_);
                float invf = expf(-9.210340371976184f * e);
                float ang = (float)t0 * invf;
                float kq = rintf(ang * 0.15915494309189535f);
                float rr = fmaf(-kq, 6.28318548202514648f, ang);
                rr = fmaf(-kq, -1.7484556000744083e-7f, rr);
                float s, c;
                sincosf(rr, &s, &c);
                float o0 = v00 * c - v01 * s;
                float o1 = v00 * s + v01 * c;
                v00 = o0; v01 = o1;
                ang = (float)t1 * invf;
                kq = rintf(ang * 0.15915494309189535f);
                rr = fmaf(-kq, 6.28318548202514648f, ang);
                rr = fmaf(-kq, -1.7484556000744083e-7f, rr);
                sincosf(rr, &s, &c);
                o0 = v10 * c - v11 * s;
                o1 = v10 * s + v11 * c;
                v10 = o0; v11 = o1;
                if (sel == 0) { v00 *= QSC; v01 *= QSC; v10 *= QSC; v11 *= QSC; }
            }
            __nv_bfloat16* oh = (sel == 0) ? qh : ((sel == 1) ? kh : vh);
            __nv_bfloat16* ol = (sel == 0) ? ql : ((sel == 1) ? kl : vl);
            size_t i0 = (size_t)r0 * C_ + jj;
            size_t i1 = (size_t)(r0 + 8) * C_ + jj;
            uint32_t h0 = packbf(v00, v01);
            __nv_bfloat162 hv0 = *(__nv_bfloat162*)&h0;
            uint32_t l0 = packbf(v00 - __bfloat162float(hv0.x),
                                 v01 - __bfloat162float(hv0.y));
            uint32_t h1 = packbf(v10, v11);
            __nv_bfloat162 hv1 = *(__nv_bfloat162*)&h1;
            uint32_t l1 = packbf(v10 - __bfloat162float(hv1.x),
                                 v11 - __bfloat162float(hv1.y));
            *(uint32_t*)(oh + i0) = h0;
            *(uint32_t*)(ol + i0) = l0;
            *(uint32_t*)(oh + i1) = h1;
            *(uint32_t*)(ol + i1) = l1;
        }
    }
}

// ---------------------------------------------------------------------------
// GEMM #2: out = y @ w_proj + b_proj (fp32 out)
// ---------------------------------------------------------------------------
__global__ __launch_bounds__(GEMM_THREADS, 1)
void gemm_hmma_bf16x3(const __nv_bfloat16* __restrict__ Ah,
                      const __nv_bfloat16* __restrict__ Al,
                      const __nv_bfloat16* __restrict__ Bh,
                      const __nv_bfloat16* __restrict__ Bl,
                      const float* __restrict__ bias, float* __restrict__ Cm,
                      int N, int K)
{
    extern __shared__ char dsm[];
    const uint32_t raw = smem_u32(dsm);
    const uint32_t sb = (raw + 1023u) & ~1023u;

    const int tid = threadIdx.x;
    const int wid = tid >> 5, lane = tid & 31;
    const int wm = (wid & 1) * 64;
    const int wn = (wid >> 1) * 64;
    const int rowBase = blockIdx.y * 128;
    const int colBase = blockIdx.x * 256;

    G2_MAINLOOP(K)

    const int gro = lane >> 2, thr = lane & 3;
#pragma unroll
    for (int mi = 0; mi < 4; mi++) {
        int r0 = rowBase + wm + mi * 16 + gro;
#pragma unroll
        for (int ni = 0; ni < 8; ni++) {
            int cb = colBase + wn + ni * 8 + thr * 2;
            float bx = bias[cb], by = bias[cb + 1];
            float2 o0, o1;
            o0.x = acc[mi][ni][0] + bx; o0.y = acc[mi][ni][1] + by;
            o1.x = acc[mi][ni][2] + bx; o1.y = acc[mi][ni][3] + by;
            *(float2*)(Cm + (size_t)r0 * N + cb) = o0;
            *(float2*)(Cm + (size_t)(r0 + 8) * N + cb) = o1;
        }
    }
}

// ---------------------------------------------------------------------------
// HMMA flash attention v3 (unchanged from R12-passing version):
// 64 q-rows/CTA, 4 warps, Q fragments in registers, 32-row KV tiles
// double-buffered via cp.async, 2 CTAs/SM.
// ---------------------------------------------------------------------------
#define QSTG 0
#define QSTG_L 16384
#define KV0 32768
#define KVSTB 32768
#define KH_O 0
#define KL_O 8192
#define VH_O 16384
#define VL_O 24576
#define ATTN3_DSM (32768 + 2 * 32768 + 1024)

__global__ __launch_bounds__(128, 2)
void attn_hmma3(const __nv_bfloat16* __restrict__ qh, const __nv_bfloat16* __restrict__ ql,
                const __nv_bfloat16* __restrict__ kh, const __nv_bfloat16* __restrict__ kl,
                const __nv_bfloat16* __restrict__ vh, const __nv_bfloat16* __restrict__ vl,
                __nv_bfloat16* __restrict__ yh, __nv_bfloat16* __restrict__ yl)
{
    extern __shared__ char asmem[];
    const uint32_t raw = smem_u32(asmem);
    const uint32_t sb = (raw + 1023u) & ~1023u;

    const int qt = blockIdx.x, h = blockIdx.y, b = blockIdx.z;
    const int qb = qt * 64;
    const int tid = threadIdx.x;
    const int wid = tid >> 5, lane = tid & 31;
    const int wq0 = wid * 16;
    const int lrow = lane & 15;
    const int lch = (lane >> 4) * 16;
    const int gro = lane >> 2, thr = lane & 3;
    const uint32_t rx = ((uint32_t)(lrow & 7)) << 4;

#pragma unroll
    for (int rep = 0; rep < 8; rep++) {
        int idx = tid + rep * 128;
        int row = idx >> 4, ch = idx & 15;
        uint32_t so = (uint32_t)row * 256 +
                      (((uint32_t)(ch * 16)) ^ (((uint32_t)(row & 7)) << 4));
        size_t g = ((size_t)(b * T_ + qb + row)) * C_ + h * DH + ch * 8;
        cpa16(sb + QSTG + so, qh + g);
        cpa16(sb + QSTG_L + so, ql + g);
    }
    CP_COMMIT();

    auto loadKV = [&](int st, int j2) {
        uint32_t stb = sb + KV0 + st * KVSTB;
        size_t grow = ((size_t)(b * T_ + j2 * 32)) * C_ + h * DH;
#pragma unroll
        for (int rep = 0; rep < 4; rep++) {
            int idx = tid + rep * 128;
            int row = idx >> 4, ch = idx & 15;
            uint32_t so = (uint32_t)row * 256 +
                          (((uint32_t)(ch * 16)) ^ (((uint32_t)(row & 7)) << 4));
            size_t g = grow + (size_t)row * C_ + ch * 8;
            cpa16(stb + KH_O + so, kh + g);
            cpa16(stb + KL_O + so, kl + g);
            cpa16(stb + VH_O + so, vh + g);
            cpa16(stb + VL_O + so, vl + g);
        }
    };

    loadKV(0, 0);
    CP_COMMIT();

    CP_WAIT1();
    __syncthreads();
    uint32_t aqh[8][4], aql[8][4];
#pragma unroll
    for (int kc = 0; kc < 8; kc++) {
        uint32_t off = (uint32_t)(wq0 + lrow) * 256 +
                       (((uint32_t)(kc * 32 + lch)) ^ rx);
        ldm4(aqh[kc], sb + QSTG + off);
        ldm4(aql[kc], sb + QSTG_L + off);
    }

    float m0 = -INFINITY, m1 = -INFINITY, l0 = 0.f, l1 = 0.f;
    float O[16][4];
#pragma unroll
    for (int i = 0; i < 16; i++)
#pragma unroll
        for (int e = 0; e < 4; e++) O[i][e] = 0.f;

    const int ntiles = 2 * qt + 2;
    for (int j = 0; j < ntiles; j++) {
        const int kvg = j * 32;
        if (j + 1 < ntiles) {
            loadKV((j + 1) & 1, j + 1);
            CP_COMMIT();
            CP_WAIT1();
        } else {
            CP_WAIT0();
        }
        __syncthreads();

        const uint32_t stb = sb + KV0 + (j & 1) * KVSTB;
        const uint32_t sKH = stb + KH_O, sKL = stb + KL_O;
        const uint32_t sVH = stb + VH_O, sVL = stb + VL_O;

        float c[4][4];
#pragma unroll
        for (int nt = 0; nt < 4; nt++)
#pragma unroll
            for (int e = 0; e < 4; e++) c[nt][e] = 0.f;

#pragma unroll
        for (int kc = 0; kc < 8; kc++) {
            const uint32_t kb = (uint32_t)(kc * 32 + lch);
#pragma unroll
            for (int g4 = 0; g4 < 2; g4++) {
                uint32_t off = (uint32_t)(g4 * 16 + lrow) * 256 + (kb ^ rx);
                uint32_t bh[4], bl[4];
                ldm4(bh, sKH + off);
                ldm4(bl, sKL + off);
#pragma unroll
                for (int hf = 0; hf < 2; hf++) {
                    int nt = g4 * 2 + hf;
                    mma16816(c[nt], aqh[kc], bh[hf], bh[hf + 2]);
                    mma16816(c[nt], aqh[kc], bl[hf], bl[hf + 2]);
                    mma16816(c[nt], aql[kc], bh[hf], bh[hf + 2]);
                }
            }
        }

        const int row_lo = qb + wq0 + gro;
        const int row_hi = row_lo + 8;
        if (kvg + 31 > qb + wq0) {
#pragma unroll
            for (int nt = 0; nt < 4; nt++) {
                int cbase = kvg + nt * 8 + 2 * thr;
                if (cbase > row_lo)     c[nt][0] = -1e30f;
                if (cbase + 1 > row_lo) c[nt][1] = -1e30f;
                if (cbase > row_hi)     c[nt][2] = -1e30f;
                if (cbase + 1 > row_hi) c[nt][3] = -1e30f;
            }
        }

        float mt0 = -1e30f, mt1 = -1e30f;
#pragma unroll
        for (int nt = 0; nt < 4; nt++) {
            mt0 = fmaxf(mt0, fmaxf(c[nt][0], c[nt][1]));
            mt1 = fmaxf(mt1, fmaxf(c[nt][2], c[nt][3]));
        }
        mt0 = fmaxf(mt0, __shfl_xor_sync(0xffffffffu, mt0, 1));
        mt0 = fmaxf(mt0, __shfl_xor_sync(0xffffffffu, mt0, 2));
        mt1 = fmaxf(mt1, __shfl_xor_sync(0xffffffffu, mt1, 1));
        mt1 = fmaxf(mt1, __shfl_xor_sync(0xffffffffu, mt1, 2));
        float mn0 = fmaxf(m0, mt0), mn1 = fmaxf(m1, mt1);
        float cor0 = ex2f(m0 - mn0), cor1 = ex2f(m1 - mn1);
        float s0 = 0.f, s1 = 0.f;
#pragma unroll
        for (int nt = 0; nt < 4; nt++) {
            c[nt][0] = ex2f(c[nt][0] - mn0); s0 += c[nt][0];
            c[nt][1] = ex2f(c[nt][1] - mn0); s0 += c[nt][1];
            c[nt][2] = ex2f(c[nt][2] - mn1); s1 += c[nt][2];
            c[nt][3] = ex2f(c[nt][3] - mn1); s1 += c[nt][3];
        }
        s0 += __shfl_xor_sync(0xffffffffu, s0, 1);
        s0 += __shfl_xor_sync(0xffffffffu, s0, 2);
        s1 += __shfl_xor_sync(0xffffffffu, s1, 1);
        s1 += __shfl_xor_sync(0xffffffffu, s1, 2);
        l0 = l0 * cor0 + s0; m0 = mn0;
        l1 = l1 * cor1 + s1; m1 = mn1;
#pragma unroll
        for (int i = 0; i < 16; i++) {
            O[i][0] *= cor0; O[i][1] *= cor0;
            O[i][2] *= cor1; O[i][3] *= cor1;
        }

        const uint32_t rxv = ((uint32_t)(lane & 7)) << 4;
        const uint32_t colb = (uint32_t)((lane >> 3) & 1) * 16;
#pragma unroll
        for (int kc2 = 0; kc2 < 2; kc2++) {
            uint32_t aph[4], apl[4];
            {
                float p00 = c[2 * kc2][0], p01 = c[2 * kc2][1];
                float p10 = c[2 * kc2][2], p11 = c[2 * kc2][3];
                float p20 = c[2 * kc2 + 1][0], p21 = c[2 * kc2 + 1][1];
                float p30 = c[2 * kc2 + 1][2], p31 = c[2 * kc2 + 1][3];
                aph[0] = packbf(p00, p01);
                aph[1] = packbf(p10, p11);
                aph[2] = packbf(p20, p21);
                aph[3] = packbf(p30, p31);
                __nv_bfloat162* t;
                t = (__nv_bfloat162*)&aph[0];
                apl[0] = packbf(p00 - __bfloat162float(t->x), p01 - __bfloat162float(t->y));
                t = (__nv_bfloat162*)&aph[1];
                apl[1] = packbf(p10 - __bfloat162float(t->x), p11 - __bfloat162float(t->y));
                t = (__nv_bfloat162*)&aph[2];
                apl[2] = packbf(p20 - __bfloat162float(t->x), p21 - __bfloat162float(t->y));
                t = (__nv_bfloat162*)&aph[3];
                apl[3] = packbf(p30 - __bfloat162float(t->x), p31 - __bfloat162float(t->y));
            }
            const uint32_t vrow = (uint32_t)(kc2 * 16 + (lane & 7) + (lane >> 4) * 8);
#pragma unroll
            for (int gg = 0; gg < 8; gg++) {
                uint32_t off = vrow * 256 + (((uint32_t)(gg * 32) + colb) ^ rxv);
                uint32_t vhf[4], vlf[4];
                ldm4t(vhf, sVH + off);
                ldm4t(vlf, sVL + off);
#pragma unroll
                for (int hf = 0; hf < 2; hf++) {
                    int nt2 = gg * 2 + hf;
                    mma16816(O[nt2], aph, vhf[hf], vhf[hf + 2]);
                    mma16816(O[nt2], aph, vlf[hf], vlf[hf + 2]);
                    mma16816(O[nt2], apl, vhf[hf], vhf[hf + 2]);
                }
            }
        }
        __syncthreads();
    }

    const float il0 = 1.f / l0, il1 = 1.f / l1;
    const int row_lo = qb + wq0 + gro;
    size_t r0o = (size_t)(b * T_ + row_lo) * C_;
    size_t r1o = (size_t)(b * T_ + row_lo + 8) * C_;
#pragma unroll
    for (int nt2 = 0; nt2 < 16; nt2++) {
        int col = h * DH + nt2 * 8 + 2 * thr;
        float a0 = O[nt2][0] * il0, a1 = O[nt2][1] * il0;
        float b0 = O[nt2][2] * il1, b1 = O[nt2][3] * il1;
        uint32_t h0 = packbf(a0, a1);
        __nv_bfloat162 hv0 = *(__nv_bfloat162*)&h0;
        uint32_t l0w = packbf(a0 - __bfloat162float(hv0.x), a1 - __bfloat162float(hv0.y));
        uint32_t h1 = packbf(b0, b1);
        __nv_bfloat162 hv1 = *(__nv_bfloat162*)&h1;
        uint32_t l1w = packbf(b0 - __bfloat162float(hv1.x), b1 - __bfloat162float(hv1.y));
        *(uint32_t*)(yh + r0o + col) = h0;
        *(uint32_t*)(yl + r0o + col) = l0w;
        *(uint32_t*)(yh + r1o + col) = h1;
        *(uint32_t*)(yl + r1o + col) = l1w;
    }
}

// ---------------------------------------------------------------------------
// Launch
// ---------------------------------------------------------------------------
extern "C" void kernel_launch(void* const* d_in, const int* in_sizes, int n_in,
                              void* d_out, int out_size)
{
    (void)in_sizes; (void)n_in; (void)out_size;
    const float* x      = (const float*)d_in[0];
    const float* w_qkv  = (const float*)d_in[1];
    const float* b_qkv  = (const float*)d_in[2];
    const float* w_proj = (const float*)d_in[3];
    const float* b_proj = (const float*)d_in[4];
    float* out = (float*)d_out;

    void *p_xh, *p_xl, *p_yh, *p_yl, *p_wqh, *p_wql, *p_wph, *p_wpl;
    void *p_qh, *p_ql, *p_kh, *p_kl, *p_vh, *p_vl;
    cudaGetSymbolAddress(&p_xh, g_xc_h);
    cudaGetSymbolAddress(&p_xl, g_xc_l);
    cudaGetSymbolAddress(&p_yh, g_yc_h);
    cudaGetSymbolAddress(&p_yl, g_yc_l);
    cudaGetSymbolAddress(&p_wqh, g_wq_h);
    cudaGetSymbolAddress(&p_wql, g_wq_l);
    cudaGetSymbolAddress(&p_wph, g_wp_h);
    cudaGetSymbolAddress(&p_wpl, g_wp_l);
    cudaGetSymbolAddress(&p_qh, g_qh);
    cudaGetSymbolAddress(&p_ql, g_ql);
    cudaGetSymbolAddress(&p_kh, g_kh);
    cudaGetSymbolAddress(&p_kl, g_kl);
    cudaGetSymbolAddress(&p_vh, g_vh);
    cudaGetSymbolAddress(&p_vl, g_vl);

    cudaFuncSetAttribute(gemm_qkv_rope,
                         cudaFuncAttributeMaxDynamicSharedMemorySize, G2_DSM);
    cudaFuncSetAttribute(gemm_hmma_bf16x3,
                         cudaFuncAttributeMaxDynamicSharedMemorySize, G2_DSM);
    cudaFuncSetAttribute(attn_hmma3,
                         cudaFuncAttributeMaxDynamicSharedMemorySize, ATTN3_DSM);

    // 0) Weight transpose+split and x split
    wconv<<<dim3(THREE_C / 32, C_ / 32), dim3(32, 8)>>>(
        w_qkv, (__nv_bfloat16*)p_wqh, (__nv_bfloat16*)p_wql, C_, THREE_C);
    wconv<<<dim3(C_ / 32, C_ / 32), dim3(32, 8)>>>(
        w_proj, (__nv_bfloat16*)p_wph, (__nv_bfloat16*)p_wpl, C_, C_);
    {
        long n8 = (long)M_ * C_ / 8;
        convert_hilo<<<(int)((n8 + 255) / 256), 256>>>(
            x, (__nv_bfloat16*)p_xh, (__nv_bfloat16*)p_xl, n8);
    }

    // 1) QKV GEMM (CTA 128x256) + fused bias + RoPE + scale + hi/lo split
    gemm_qkv_rope<<<dim3(THREE_C / 256, M_ / 128), GEMM_THREADS, G2_DSM>>>(
        (const __nv_bfloat16*)p_xh, (const __nv_bfloat16*)p_xl,
        (const __nv_bfloat16*)p_wqh, (const __nv_bfloat16*)p_wql,
        b_qkv,
        (__nv_bfloat16*)p_qh, (__nv_bfloat16*)p_ql,
        (__nv_bfloat16*)p_kh, (__nv_bfloat16*)p_kl,
        (__nv_bfloat16*)p_vh, (__nv_bfloat16*)p_vl);

    // 2) Causal flash attention (HMMA bf16x3, 2 CTA/SM, Q in regs) -> y hi/lo
    {
        dim3 grid(T_ / 64, H_, B_);
        attn_hmma3<<<grid, 128, ATTN3_DSM>>>(
            (const __nv_bfloat16*)p_qh, (const __nv_bfloat16*)p_ql,
            (const __nv_bfloat16*)p_kh, (const __nv_bfloat16*)p_kl,
            (const __nv_bfloat16*)p_vh, (const __nv_bfloat16*)p_vl,
            (__nv_bfloat16*)p_yh, (__nv_bfloat16*)p_yl);
    }

    // 3) out = y @ w_proj + b_proj (CTA 128x256, fp32 out)
    gemm_hmma_bf16x3<<<dim3(C_ / 256, M_ / 128), GEMM_THREADS, G2_DSM>>>(
        (const __nv_bfloat16*)p_yh, (const __nv_bfloat16*)p_yl,
        (const __nv_bfloat16*)p_wph, (const __nv_bfloat16*)p_wpl,
        b_proj, out, C_, C_);
}

// round 14
// speedup vs baseline: 1.6803x; 1.6803x over previous
#include <cuda_runtime.h>
#include <cuda_bf16.h>
#include <math.h>
#include <stdint.h>

// Problem constants
#define B_ 4
#define T_ 2048
#define C_ 2048
#define H_ 16
#define DH 128
#define THREE_C (3 * C_)
#define M_ (B_ * T_)   // 8192

// ---------------------------------------------------------------------------
// Device-global scratch (allocation-free)
// ---------------------------------------------------------------------------
__device__ __nv_bfloat16 g_xc_h[(size_t)M_ * C_];
__device__ __nv_bfloat16 g_xc_l[(size_t)M_ * C_];
__device__ __nv_bfloat16 g_yc_h[(size_t)M_ * C_];
__device__ __nv_bfloat16 g_yc_l[(size_t)M_ * C_];
__device__ __nv_bfloat16 g_wq_h[(size_t)THREE_C * C_];      // w_qkv^T [6144,2048]
__device__ __nv_bfloat16 g_wq_l[(size_t)THREE_C * C_];
__device__ __nv_bfloat16 g_wp_h[(size_t)C_ * C_];           // w_proj^T [2048,2048]
__device__ __nv_bfloat16 g_wp_l[(size_t)C_ * C_];
// Roped/scaled bf16 hi/lo Q,K and split V, layout [M_][C_] (c = h*128+d)
__device__ __nv_bfloat16 g_qh[(size_t)M_ * C_];
__device__ __nv_bfloat16 g_ql[(size_t)M_ * C_];
__device__ __nv_bfloat16 g_kh[(size_t)M_ * C_];
__device__ __nv_bfloat16 g_kl[(size_t)M_ * C_];
__device__ __nv_bfloat16 g_vh[(size_t)M_ * C_];
__device__ __nv_bfloat16 g_vl[(size_t)M_ * C_];

// ---------------------------------------------------------------------------
// Helpers
// ---------------------------------------------------------------------------
__device__ __forceinline__ uint32_t smem_u32(const void* p) {
    uint32_t a;
    asm("{ .reg .u64 t; cvta.to.shared.u64 t, %1; cvt.u32.u64 %0, t; }"
        : "=r"(a) : "l"(p));
    return a;
}
static __device__ __forceinline__ uint32_t sw128(uint32_t x) {
    return x ^ ((x >> 3) & 0x70);
}
__device__ __forceinline__ void cpa16(uint32_t s, const void* g) {
    asm volatile("cp.async.cg.shared.global [%0], [%1], 16;" :: "r"(s), "l"(g));
}
#define CP_COMMIT() asm volatile("cp.async.commit_group;" ::: "memory")
#define CP_WAIT1()  asm volatile("cp.async.wait_group 1;" ::: "memory")
#define CP_WAIT0()  asm volatile("cp.async.wait_group 0;" ::: "memory")

__device__ __forceinline__ void ldm4(uint32_t* r, uint32_t addr) {
    asm volatile("ldmatrix.sync.aligned.m8n8.x4.shared.b16 {%0,%1,%2,%3}, [%4];"
                 : "=r"(r[0]), "=r"(r[1]), "=r"(r[2]), "=r"(r[3]) : "r"(addr));
}
__device__ __forceinline__ void ldm4t(uint32_t* r, uint32_t addr) {
    asm volatile("ldmatrix.sync.aligned.m8n8.x4.trans.shared.b16 {%0,%1,%2,%3}, [%4];"
                 : "=r"(r[0]), "=r"(r[1]), "=r"(r[2]), "=r"(r[3]) : "r"(addr));
}
__device__ __forceinline__ void mma16816(float* d, const uint32_t* a,
                                         uint32_t b0, uint32_t b1) {
    asm volatile(
        "mma.sync.aligned.m16n8k16.row.col.f32.bf16.bf16.f32 "
        "{%0,%1,%2,%3}, {%4,%5,%6,%7}, {%8,%9}, {%0,%1,%2,%3};"
        : "+f"(d[0]), "+f"(d[1]), "+f"(d[2]), "+f"(d[3])
        : "r"(a[0]), "r"(a[1]), "r"(a[2]), "r"(a[3]), "r"(b0), "r"(b1));
}
__device__ __forceinline__ uint32_t packbf(float a, float b) {
    __nv_bfloat162 t = __floats2bfloat162_rn(a, b);   // .x = a (low 16 bits)
    return *(uint32_t*)&t;
}
__device__ __forceinline__ float ex2f(float x) {
    float r;
    asm("ex2.approx.f32 %0, %1;" : "=f"(r) : "f"(x));
    return r;
}

// ---------------------------------------------------------------------------
// Elementwise fp32 -> bf16 (hi, lo) split. n8 = elements/8.
// ---------------------------------------------------------------------------
__global__ void convert_hilo(const float* __restrict__ X,
                             __nv_bfloat16* __restrict__ Hh,
                             __nv_bfloat16* __restrict__ Hl, long n8)
{
    long i = (long)blockIdx.x * blockDim.x + threadIdx.x;
    if (i >= n8) return;
    float4 a = ((const float4*)X)[i * 2 + 0];
    float4 b = ((const float4*)X)[i * 2 + 1];
    float v[8] = {a.x, a.y, a.z, a.w, b.x, b.y, b.z, b.w};
    union { __nv_bfloat16 e[8]; uint4 u; } ph, pl;
#pragma unroll
    for (int j = 0; j < 8; j++) {
        __nv_bfloat16 h = __float2bfloat16(v[j]);
        ph.e[j] = h;
        pl.e[j] = __float2bfloat16(v[j] - __bfloat162float(h));
    }
    ((uint4*)Hh)[i] = ph.u;
    ((uint4*)Hl)[i] = pl.u;
}

// ---------------------------------------------------------------------------
// Transpose + split: W[K,N] fp32 row-major -> Th/Tl [N,K] bf16 row-major
// ---------------------------------------------------------------------------
__global__ void wconv(const float* __restrict__ W, __nv_bfloat16* __restrict__ Th,
                      __nv_bfloat16* __restrict__ Tl, int K, int N)
{
    __shared__ float ts[32][33];
    int n0 = blockIdx.x * 32, k0 = blockIdx.y * 32;
    int tx = threadIdx.x, ty = threadIdx.y;
    for (int i = ty; i < 32; i += 8)
        ts[i][tx] = W[(size_t)(k0 + i) * N + n0 + tx];
    __syncthreads();
    for (int i = ty; i < 32; i += 8) {
        float v = ts[tx][i];
        __nv_bfloat16 h = __float2bfloat16(v);
        __nv_bfloat16 l = __float2bfloat16(v - __bfloat162float(h));
        size_t o = (size_t)(n0 + i) * K + k0 + tx;
        Th[o] = h;
        Tl[o] = l;
    }
}

// ---------------------------------------------------------------------------
// GEMM v3 config: CTA 128x128, 512 threads (16 warps, 4x4 grid), warp tile
// 32x32, BK=64, 3-stage cp.async. Same smem layout & math as R12; the extra
// warps (4/SMSP) hide barrier/ldsm latency that capped tensor at 65%.
// acc = 32 regs/thread -> no spill risk.
// ---------------------------------------------------------------------------
#define GEMM_THREADS 512
#define BKc 64
#define A_H_OFF 0
#define A_L_OFF 16384
#define B_H_OFF 32768
#define B_L_OFF 49152
#define STG_BYTES 65536
#define STAGES 3
#define GEMM_DSM (STAGES * STG_BYTES + 1024)

#define G3_MAINLOOP(K_)                                                        \
    const int nch = (K_) / BKc;                                                \
    auto load_stage = [&](int st, int k0) {                                    \
        uint32_t sbase = sb + st * STG_BYTES;                                  \
        _Pragma("unroll")                                                      \
        for (int rep = 0; rep < 2; rep++) {                                    \
            int i = tid + rep * GEMM_THREADS;                                  \
            int row = i >> 3, cc = i & 7;                                      \
            uint32_t so = sw128((uint32_t)(row * 128 + cc * 16));              \
            size_t ga = (size_t)(rowBase + row) * (K_) + k0 + cc * 8;          \
            size_t gb = (size_t)(colBase + row) * (K_) + k0 + cc * 8;          \
            cpa16(sbase + A_H_OFF + so, Ah + ga);                              \
            cpa16(sbase + A_L_OFF + so, Al + ga);                              \
            cpa16(sbase + B_H_OFF + so, Bh + gb);                              \
            cpa16(sbase + B_L_OFF + so, Bl + gb);                              \
        }                                                                      \
    };                                                                         \
    load_stage(0, 0); CP_COMMIT();                                             \
    load_stage(1, BKc); CP_COMMIT();                                           \
    float acc[2][4][4];                                                        \
    _Pragma("unroll")                                                          \
    for (int mi = 0; mi < 2; mi++)                                             \
        _Pragma("unroll")                                                      \
        for (int ni = 0; ni < 4; ni++)                                         \
            _Pragma("unroll")                                                  \
            for (int e = 0; e < 4; e++) acc[mi][ni][e] = 0.f;                  \
    const int lrow = lane & 15;                                                \
    const int lchunk = (lane >> 4) * 16;                                       \
    for (int c = 0; c < nch; c++) {                                            \
        CP_WAIT1();                                                            \
        __syncthreads();                                                       \
        int cn = c + STAGES - 1;                                               \
        if (cn < nch) load_stage(cn % STAGES, cn * BKc);                       \
        CP_COMMIT();                                                           \
        const uint32_t sbase = sb + (c % STAGES) * STG_BYTES;                  \
        _Pragma("unroll")                                                      \
        for (int ks = 0; ks < 4; ks++) {                                       \
            const int kb = ks * 32 + lchunk;                                   \
            uint32_t bh[2][4], bl[2][4];                                       \
            _Pragma("unroll")                                                  \
            for (int g = 0; g < 2; g++) {                                      \
                uint32_t bo = sw128((uint32_t)((wn + g * 16 + lrow) * 128 + kb)); \
                ldm4(bh[g], sbase + B_H_OFF + bo);                             \
                ldm4(bl[g], sbase + B_L_OFF + bo);                             \
            }                                                                  \
            _Pragma("unroll")                                                  \
            for (int mi = 0; mi < 2; mi++) {                                   \
                uint32_t ah[4], al[4];                                         \
                uint32_t ao = sw128((uint32_t)((wm + mi * 16 + lrow) * 128 + kb)); \
                ldm4(ah, sbase + A_H_OFF + ao);                                \
                ldm4(al, sbase + A_L_OFF + ao);                                \
                _Pragma("unroll")                                              \
                for (int ni = 0; ni < 4; ni++) {                               \
                    int g = ni >> 1, hf = ni & 1;                              \
                    mma16816(acc[mi][ni], ah, bh[g][hf], bh[g][hf + 2]);       \
                    mma16816(acc[mi][ni], ah, bl[g][hf], bl[g][hf + 2]);       \
                    mma16816(acc[mi][ni], al, bh[g][hf], bh[g][hf + 2]);       \
                }                                                              \
            }                                                                  \
        }                                                                      \
        __syncthreads();                                                       \
    }

// ---------------------------------------------------------------------------
// GEMM #1: out = x @ w_qkv + b_qkv, epilogue RoPE + q scale + bf16 hi/lo split
// ---------------------------------------------------------------------------
__global__ __launch_bounds__(GEMM_THREADS, 1)
void gemm_qkv_rope(const __nv_bfloat16* __restrict__ Ah,
                   const __nv_bfloat16* __restrict__ Al,
                   const __nv_bfloat16* __restrict__ Bh,
                   const __nv_bfloat16* __restrict__ Bl,
                   const float* __restrict__ bias,
                   __nv_bfloat16* __restrict__ qh, __nv_bfloat16* __restrict__ ql,
                   __nv_bfloat16* __restrict__ kh, __nv_bfloat16* __restrict__ kl,
                   __nv_bfloat16* __restrict__ vh, __nv_bfloat16* __restrict__ vl)
{
    extern __shared__ char dsm[];
    const uint32_t raw = smem_u32(dsm);
    const uint32_t sb = (raw + 1023u) & ~1023u;

    const int tid = threadIdx.x;
    const int wid = tid >> 5, lane = tid & 31;
    const int wm = (wid & 3) * 32;        // 4 m-warps x 32 rows
    const int wn = (wid >> 2) * 32;       // 4 n-warps x 32 cols
    const int rowBase = blockIdx.y * 128;
    const int colBase = blockIdx.x * 128;

    G3_MAINLOOP(C_)

    // Epilogue: bias, RoPE on q/k pairs, q scale (1/sqrt(dh))*log2e, split hi/lo
    const float QSC = 0.08838834764831845f * 1.4426950408889634f;
    const int gro = lane >> 2, thr = lane & 3;
#pragma unroll
    for (int mi = 0; mi < 2; mi++) {
        int r0 = rowBase + wm + mi * 16 + gro;
        int t0 = r0 & (T_ - 1), t1 = (r0 + 8) & (T_ - 1);
#pragma unroll
        for (int ni = 0; ni < 4; ni++) {
            int cb = colBase + wn + ni * 8 + thr * 2;   // even
            int sel = cb >> 11;          // 0=q, 1=k, 2=v
            int jj = cb & 2047;
            float bx = bias[cb], by = bias[cb + 1];
            float v00 = acc[mi][ni][0] + bx, v01 = acc[mi][ni][1] + by;
            float v10 = acc[mi][ni][2] + bx, v11 = acc[mi][ni][3] + by;
            if (sel < 2) {
                float e = (float)jj * (1.0f / (float)C_);
                float invf = expf(-9.210340371976184f * e);
                float ang = (float)t0 * invf;
                float kq = rintf(ang * 0.15915494309189535f);
                float rr = fmaf(-kq, 6.28318548202514648f, ang);
                rr = fmaf(-kq, -1.7484556000744083e-7f, rr);
                float s, c;
                sincosf(rr, &s, &c);
                float o0 = v00 * c - v01 * s;
                float o1 = v00 * s + v01 * c;
                v00 = o0; v01 = o1;
                ang = (float)t1 * invf;
                kq = rintf(ang * 0.15915494309189535f);
                rr = fmaf(-kq, 6.28318548202514648f, ang);
                rr = fmaf(-kq, -1.7484556000744083e-7f, rr);
                sincosf(rr, &s, &c);
                o0 = v10 * c - v11 * s;
                o1 = v10 * s + v11 * c;
                v10 = o0; v11 = o1;
                if (sel == 0) { v00 *= QSC; v01 *= QSC; v10 *= QSC; v11 *= QSC; }
            }
            __nv_bfloat16* oh = (sel == 0) ? qh : ((sel == 1) ? kh : vh);
            __nv_bfloat16* ol = (sel == 0) ? ql : ((sel == 1) ? kl : vl);
            size_t i0 = (size_t)r0 * C_ + jj;
            size_t i1 = (size_t)(r0 + 8) * C_ + jj;
            uint32_t h0 = packbf(v00, v01);
            __nv_bfloat162 hv0 = *(__nv_bfloat162*)&h0;
            uint32_t l0 = packbf(v00 - __bfloat162float(hv0.x),
                                 v01 - __bfloat162float(hv0.y));
            uint32_t h1 = packbf(v10, v11);
            __nv_bfloat162 hv1 = *(__nv_bfloat162*)&h1;
            uint32_t l1 = packbf(v10 - __bfloat162float(hv1.x),
                                 v11 - __bfloat162float(hv1.y));
            *(uint32_t*)(oh + i0) = h0;
            *(uint32_t*)(ol + i0) = l0;
            *(uint32_t*)(oh + i1) = h1;
            *(uint32_t*)(ol + i1) = l1;
        }
    }
}

// ---------------------------------------------------------------------------
// GEMM #2: out = y @ w_proj + b_proj (fp32 out)
// ---------------------------------------------------------------------------
__global__ __launch_bounds__(GEMM_THREADS, 1)
void gemm_hmma_bf16x3(const __nv_bfloat16* __restrict__ Ah,
                      const __nv_bfloat16* __restrict__ Al,
                      const __nv_bfloat16* __restrict__ Bh,
                      const __nv_bfloat16* __restrict__ Bl,
                      const float* __restrict__ bias, float* __restrict__ Cm,
                      int N, int K)
{
    extern __shared__ char dsm[];
    const uint32_t raw = smem_u32(dsm);
    const uint32_t sb = (raw + 1023u) & ~1023u;

    const int tid = threadIdx.x;
    const int wid = tid >> 5, lane = tid & 31;
    const int wm = (wid & 3) * 32;
    const int wn = (wid >> 2) * 32;
    const int rowBase = blockIdx.y * 128;
    const int colBase = blockIdx.x * 128;

    G3_MAINLOOP(K)

    const int gro = lane >> 2, thr = lane & 3;
#pragma unroll
    for (int mi = 0; mi < 2; mi++) {
        int r0 = rowBase + wm + mi * 16 + gro;
#pragma unroll
        for (int ni = 0; ni < 4; ni++) {
            int cb = colBase + wn + ni * 8 + thr * 2;
            float bx = bias[cb], by = bias[cb + 1];
            float2 o0, o1;
            o0.x = acc[mi][ni][0] + bx; o0.y = acc[mi][ni][1] + by;
            o1.x = acc[mi][ni][2] + bx; o1.y = acc[mi][ni][3] + by;
            *(float2*)(Cm + (size_t)r0 * N + cb) = o0;
            *(float2*)(Cm + (size_t)(r0 + 8) * N + cb) = o1;
        }
    }
}

// ---------------------------------------------------------------------------
// HMMA flash attention v3 (unchanged from R12-passing version):
// 64 q-rows/CTA, 4 warps, Q fragments in registers, 32-row KV tiles
// double-buffered via cp.async, 2 CTAs/SM.
// ---------------------------------------------------------------------------
#define QSTG 0
#define QSTG_L 16384
#define KV0 32768
#define KVSTB 32768
#define KH_O 0
#define KL_O 8192
#define VH_O 16384
#define VL_O 24576
#define ATTN3_DSM (32768 + 2 * 32768 + 1024)

__global__ __launch_bounds__(128, 2)
void attn_hmma3(const __nv_bfloat16* __restrict__ qh, const __nv_bfloat16* __restrict__ ql,
                const __nv_bfloat16* __restrict__ kh, const __nv_bfloat16* __restrict__ kl,
                const __nv_bfloat16* __restrict__ vh, const __nv_bfloat16* __restrict__ vl,
                __nv_bfloat16* __restrict__ yh, __nv_bfloat16* __restrict__ yl)
{
    extern __shared__ char asmem[];
    const uint32_t raw = smem_u32(asmem);
    const uint32_t sb = (raw + 1023u) & ~1023u;

    const int qt = blockIdx.x, h = blockIdx.y, b = blockIdx.z;
    const int qb = qt * 64;
    const int tid = threadIdx.x;
    const int wid = tid >> 5, lane = tid & 31;
    const int wq0 = wid * 16;
    const int lrow = lane & 15;
    const int lch = (lane >> 4) * 16;
    const int gro = lane >> 2, thr = lane & 3;
    const uint32_t rx = ((uint32_t)(lrow & 7)) << 4;

#pragma unroll
    for (int rep = 0; rep < 8; rep++) {
        int idx = tid + rep * 128;
        int row = idx >> 4, ch = idx & 15;
        uint32_t so = (uint32_t)row * 256 +
                      (((uint32_t)(ch * 16)) ^ (((uint32_t)(row & 7)) << 4));
        size_t g = ((size_t)(b * T_ + qb + row)) * C_ + h * DH + ch * 8;
        cpa16(sb + QSTG + so, qh + g);
        cpa16(sb + QSTG_L + so, ql + g);
    }
    CP_COMMIT();

    auto loadKV = [&](int st, int j2) {
        uint32_t stb = sb + KV0 + st * KVSTB;
        size_t grow = ((size_t)(b * T_ + j2 * 32)) * C_ + h * DH;
#pragma unroll
        for (int rep = 0; rep < 4; rep++) {
            int idx = tid + rep * 128;
            int row = idx >> 4, ch = idx & 15;
            uint32_t so = (uint32_t)row * 256 +
                          (((uint32_t)(ch * 16)) ^ (((uint32_t)(row & 7)) << 4));
            size_t g = grow + (size_t)row * C_ + ch * 8;
            cpa16(stb + KH_O + so, kh + g);
            cpa16(stb + KL_O + so, kl + g);
            cpa16(stb + VH_O + so, vh + g);
            cpa16(stb + VL_O + so, vl + g);
        }
    };

    loadKV(0, 0);
    CP_COMMIT();

    CP_WAIT1();
    __syncthreads();
    uint32_t aqh[8][4], aql[8][4];
#pragma unroll
    for (int kc = 0; kc < 8; kc++) {
        uint32_t off = (uint32_t)(wq0 + lrow) * 256 +
                       (((uint32_t)(kc * 32 + lch)) ^ rx);
        ldm4(aqh[kc], sb + QSTG + off);
        ldm4(aql[kc], sb + QSTG_L + off);
    }

    float m0 = -INFINITY, m1 = -INFINITY, l0 = 0.f, l1 = 0.f;
    float O[16][4];
#pragma unroll
    for (int i = 0; i < 16; i++)
#pragma unroll
        for (int e = 0; e < 4; e++) O[i][e] = 0.f;

    const int ntiles = 2 * qt + 2;
    for (int j = 0; j < ntiles; j++) {
        const int kvg = j * 32;
        if (j + 1 < ntiles) {
            loadKV((j + 1) & 1, j + 1);
            CP_COMMIT();
            CP_WAIT1();
        } else {
            CP_WAIT0();
        }
        __syncthreads();

        const uint32_t stb = sb + KV0 + (j & 1) * KVSTB;
        const uint32_t sKH = stb + KH_O, sKL = stb + KL_O;
        const uint32_t sVH = stb + VH_O, sVL = stb + VL_O;

        float c[4][4];
#pragma unroll
        for (int nt = 0; nt < 4; nt++)
#pragma unroll
            for (int e = 0; e < 4; e++) c[nt][e] = 0.f;

#pragma unroll
        for (int kc = 0; kc < 8; kc++) {
            const uint32_t kb = (uint32_t)(kc * 32 + lch);
#pragma unroll
            for (int g4 = 0; g4 < 2; g4++) {
                uint32_t off = (uint32_t)(g4 * 16 + lrow) * 256 + (kb ^ rx);
                uint32_t bh[4], bl[4];
                ldm4(bh, sKH + off);
                ldm4(bl, sKL + off);
#pragma unroll
                for (int hf = 0; hf < 2; hf++) {
                    int nt = g4 * 2 + hf;
                    mma16816(c[nt], aqh[kc], bh[hf], bh[hf + 2]);
                    mma16816(c[nt], aqh[kc], bl[hf], bl[hf + 2]);
                    mma16816(c[nt], aql[kc], bh[hf], bh[hf + 2]);
                }
            }
        }

        const int row_lo = qb + wq0 + gro;
        const int row_hi = row_lo + 8;
        if (kvg + 31 > qb + wq0) {
#pragma unroll
            for (int nt = 0; nt < 4; nt++) {
                int cbase = kvg + nt * 8 + 2 * thr;
                if (cbase > row_lo)     c[nt][0] = -1e30f;
                if (cbase + 1 > row_lo) c[nt][1] = -1e30f;
                if (cbase > row_hi)     c[nt][2] = -1e30f;
                if (cbase + 1 > row_hi) c[nt][3] = -1e30f;
            }
        }

        float mt0 = -1e30f, mt1 = -1e30f;
#pragma unroll
        for (int nt = 0; nt < 4; nt++) {
            mt0 = fmaxf(mt0, fmaxf(c[nt][0], c[nt][1]));
            mt1 = fmaxf(mt1, fmaxf(c[nt][2], c[nt][3]));
        }
        mt0 = fmaxf(mt0, __shfl_xor_sync(0xffffffffu, mt0, 1));
        mt0 = fmaxf(mt0, __shfl_xor_sync(0xffffffffu, mt0, 2));
        mt1 = fmaxf(mt1, __shfl_xor_sync(0xffffffffu, mt1, 1));
        mt1 = fmaxf(mt1, __shfl_xor_sync(0xffffffffu, mt1, 2));
        float mn0 = fmaxf(m0, mt0), mn1 = fmaxf(m1, mt1);
        float cor0 = ex2f(m0 - mn0), cor1 = ex2f(m1 - mn1);
        float s0 = 0.f, s1 = 0.f;
#pragma unroll
        for (int nt = 0; nt < 4; nt++) {
            c[nt][0] = ex2f(c[nt][0] - mn0); s0 += c[nt][0];
            c[nt][1] = ex2f(c[nt][1] - mn0); s0 += c[nt][1];
            c[nt][2] = ex2f(c[nt][2] - mn1); s1 += c[nt][2];
            c[nt][3] = ex2f(c[nt][3] - mn1); s1 += c[nt][3];
        }
        s0 += __shfl_xor_sync(0xffffffffu, s0, 1);
        s0 += __shfl_xor_sync(0xffffffffu, s0, 2);
        s1 += __shfl_xor_sync(0xffffffffu, s1, 1);
        s1 += __shfl_xor_sync(0xffffffffu, s1, 2);
        l0 = l0 * cor0 + s0; m0 = mn0;
        l1 = l1 * cor1 + s1; m1 = mn1;
#pragma unroll
        for (int i = 0; i < 16; i++) {
            O[i][0] *= cor0; O[i][1] *= cor0;
            O[i][2] *= cor1; O[i][3] *= cor1;
        }

        const uint32_t rxv = ((uint32_t)(lane & 7)) << 4;
        const uint32_t colb = (uint32_t)((lane >> 3) & 1) * 16;
#pragma unroll
        for (int kc2 = 0; kc2 < 2; kc2++) {
            uint32_t aph[4], apl[4];
            {
                float p00 = c[2 * kc2][0], p01 = c[2 * kc2][1];
                float p10 = c[2 * kc2][2], p11 = c[2 * kc2][3];
                float p20 = c[2 * kc2 + 1][0], p21 = c[2 * kc2 + 1][1];
                float p30 = c[2 * kc2 + 1][2], p31 = c[2 * kc2 + 1][3];
                aph[0] = packbf(p00, p01);
                aph[1] = packbf(p10, p11);
                aph[2] = packbf(p20, p21);
                aph[3] = packbf(p30, p31);
                __nv_bfloat162* t;
                t = (__nv_bfloat162*)&aph[0];
                apl[0] = packbf(p00 - __bfloat162float(t->x), p01 - __bfloat162float(t->y));
                t = (__nv_bfloat162*)&aph[1];
                apl[1] = packbf(p10 - __bfloat162float(t->x), p11 - __bfloat162float(t->y));
                t = (__nv_bfloat162*)&aph[2];
                apl[2] = packbf(p20 - __bfloat162float(t->x), p21 - __bfloat162float(t->y));
                t = (__nv_bfloat162*)&aph[3];
                apl[3] = packbf(p30 - __bfloat162float(t->x), p31 - __bfloat162float(t->y));
            }
            const uint32_t vrow = (uint32_t)(kc2 * 16 + (lane & 7) + (lane >> 4) * 8);
#pragma unroll
            for (int gg = 0; gg < 8; gg++) {
                uint32_t off = vrow * 256 + (((uint32_t)(gg * 32) + colb) ^ rxv);
                uint32_t vhf[4], vlf[4];
                ldm4t(vhf, sVH + off);
                ldm4t(vlf, sVL + off);
#pragma unroll
                for (int hf = 0; hf < 2; hf++) {
                    int nt2 = gg * 2 + hf;
                    mma16816(O[nt2], aph, vhf[hf], vhf[hf + 2]);
                    mma16816(O[nt2], aph, vlf[hf], vlf[hf + 2]);
                    mma16816(O[nt2], apl, vhf[hf], vhf[hf + 2]);
                }
            }
        }
        __syncthreads();
    }

    const float il0 = 1.f / l0, il1 = 1.f / l1;
    const int row_lo = qb + wq0 + gro;
    size_t r0o = (size_t)(b * T_ + row_lo) * C_;
    size_t r1o = (size_t)(b * T_ + row_lo + 8) * C_;
#pragma unroll
    for (int nt2 = 0; nt2 < 16; nt2++) {
        int col = h * DH + nt2 * 8 + 2 * thr;
        float a0 = O[nt2][0] * il0, a1 = O[nt2][1] * il0;
        float b0 = O[nt2][2] * il1, b1 = O[nt2][3] * il1;
        uint32_t h0 = packbf(a0, a1);
        __nv_bfloat162 hv0 = *(__nv_bfloat162*)&h0;
        uint32_t l0w = packbf(a0 - __bfloat162float(hv0.x), a1 - __bfloat162float(hv0.y));
        uint32_t h1 = packbf(b0, b1);
        __nv_bfloat162 hv1 = *(__nv_bfloat162*)&h1;
        uint32_t l1w = packbf(b0 - __bfloat162float(hv1.x), b1 - __bfloat162float(hv1.y));
        *(uint32_t*)(yh + r0o + col) = h0;
        *(uint32_t*)(yl + r0o + col) = l0w;
        *(uint32_t*)(yh + r1o + col) = h1;
        *(uint32_t*)(yl + r1o + col) = l1w;
    }
}

// ---------------------------------------------------------------------------
// Launch
// ---------------------------------------------------------------------------
extern "C" void kernel_launch(void* const* d_in, const int* in_sizes, int n_in,
                              void* d_out, int out_size)
{
    (void)in_sizes; (void)n_in; (void)out_size;
    const float* x      = (const float*)d_in[0];
    const float* w_qkv  = (const float*)d_in[1];
    const float* b_qkv  = (const float*)d_in[2];
    const float* w_proj = (const float*)d_in[3];
    const float* b_proj = (const float*)d_in[4];
    float* out = (float*)d_out;

    void *p_xh, *p_xl, *p_yh, *p_yl, *p_wqh, *p_wql, *p_wph, *p_wpl;
    void *p_qh, *p_ql, *p_kh, *p_kl, *p_vh, *p_vl;
    cudaGetSymbolAddress(&p_xh, g_xc_h);
    cudaGetSymbolAddress(&p_xl, g_xc_l);
    cudaGetSymbolAddress(&p_yh, g_yc_h);
    cudaGetSymbolAddress(&p_yl, g_yc_l);
    cudaGetSymbolAddress(&p_wqh, g_wq_h);
    cudaGetSymbolAddress(&p_wql, g_wq_l);
    cudaGetSymbolAddress(&p_wph, g_wp_h);
    cudaGetSymbolAddress(&p_wpl, g_wp_l);
    cudaGetSymbolAddress(&p_qh, g_qh);
    cudaGetSymbolAddress(&p_ql, g_ql);
    cudaGetSymbolAddress(&p_kh, g_kh);
    cudaGetSymbolAddress(&p_kl, g_kl);
    cudaGetSymbolAddress(&p_vh, g_vh);
    cudaGetSymbolAddress(&p_vl, g_vl);

    cudaFuncSetAttribute(gemm_qkv_rope,
                         cudaFuncAttributeMaxDynamicSharedMemorySize, GEMM_DSM);
    cudaFuncSetAttribute(gemm_hmma_bf16x3,
                         cudaFuncAttributeMaxDynamicSharedMemorySize, GEMM_DSM);
    cudaFuncSetAttribute(attn_hmma3,
                         cudaFuncAttributeMaxDynamicSharedMemorySize, ATTN3_DSM);

    // 0) Weight transpose+split and x split
    wconv<<<dim3(THREE_C / 32, C_ / 32), dim3(32, 8)>>>(
        w_qkv, (__nv_bfloat16*)p_wqh, (__nv_bfloat16*)p_wql, C_, THREE_C);
    wconv<<<dim3(C_ / 32, C_ / 32), dim3(32, 8)>>>(
        w_proj, (__nv_bfloat16*)p_wph, (__nv_bfloat16*)p_wpl, C_, C_);
    {
        long n8 = (long)M_ * C_ / 8;
        convert_hilo<<<(int)((n8 + 255) / 256), 256>>>(
            x, (__nv_bfloat16*)p_xh, (__nv_bfloat16*)p_xl, n8);
    }

    // 1) QKV GEMM (512 thr, warp 32x32) + bias + RoPE + scale + hi/lo split
    gemm_qkv_rope<<<dim3(THREE_C / 128, M_ / 128), GEMM_THREADS, GEMM_DSM>>>(
        (const __nv_bfloat16*)p_xh, (const __nv_bfloat16*)p_xl,
        (const __nv_bfloat16*)p_wqh, (const __nv_bfloat16*)p_wql,
        b_qkv,
        (__nv_bfloat16*)p_qh, (__nv_bfloat16*)p_ql,
        (__nv_bfloat16*)p_kh, (__nv_bfloat16*)p_kl,
        (__nv_bfloat16*)p_vh, (__nv_bfloat16*)p_vl);

    // 2) Causal flash attention (HMMA bf16x3, 2 CTA/SM, Q in regs) -> y hi/lo
    {
        dim3 grid(T_ / 64, H_, B_);
        attn_hmma3<<<grid, 128, ATTN3_DSM>>>(
            (const __nv_bfloat16*)p_qh, (const __nv_bfloat16*)p_ql,
            (const __nv_bfloat16*)p_kh, (const __nv_bfloat16*)p_kl,
            (const __nv_bfloat16*)p_vh, (const __nv_bfloat16*)p_vl,
            (__nv_bfloat16*)p_yh, (__nv_bfloat16*)p_yl);
    }

    // 3) out = y @ w_proj + b_proj (512 thr, warp 32x32, fp32 out)
    gemm_hmma_bf16x3<<<dim3(C_ / 128, M_ / 128), GEMM_THREADS, GEMM_DSM>>>(
        (const __nv_bfloat16*)p_yh, (const __nv_bfloat16*)p_yl,
        (const __nv_bfloat16*)p_wph, (const __nv_bfloat16*)p_wpl,
        b_proj, out, C_, C_);
}

// round 15
// speedup vs baseline: 1.7961x; 1.0689x over previous
#include <cuda_runtime.h>
#include <cuda_bf16.h>
#include <cuda_fp16.h>
#include <math.h>
#include <stdint.h>

// Problem constants
#define B_ 4
#define T_ 2048
#define C_ 2048
#define H_ 16
#define DH 128
#define THREE_C (3 * C_)
#define M_ (B_ * T_)   // 8192

// ---------------------------------------------------------------------------
// Device-global scratch (allocation-free)
// ---------------------------------------------------------------------------
__device__ __half g_xc_h[(size_t)M_ * C_];
__device__ __half g_xc_l[(size_t)M_ * C_];
__device__ __half g_yc_h[(size_t)M_ * C_];
__device__ __half g_yc_l[(size_t)M_ * C_];
__device__ __half g_wq_h[(size_t)THREE_C * C_];      // w_qkv^T [6144,2048]
__device__ __half g_wq_l[(size_t)THREE_C * C_];
__device__ __half g_wp_h[(size_t)C_ * C_];           // w_proj^T [2048,2048]
__device__ __half g_wp_l[(size_t)C_ * C_];
// Roped/scaled bf16 hi/lo Q,K and split V for attention, layout [M_][C_]
__device__ __nv_bfloat16 g_qh[(size_t)M_ * C_];
__device__ __nv_bfloat16 g_ql[(size_t)M_ * C_];
__device__ __nv_bfloat16 g_kh[(size_t)M_ * C_];
__device__ __nv_bfloat16 g_kl[(size_t)M_ * C_];
__device__ __nv_bfloat16 g_vh[(size_t)M_ * C_];
__device__ __nv_bfloat16 g_vl[(size_t)M_ * C_];

// ---------------------------------------------------------------------------
// Helpers
// ---------------------------------------------------------------------------
__device__ __forceinline__ uint32_t smem_u32(const void* p) {
    uint32_t a;
    asm("{ .reg .u64 t; cvta.to.shared.u64 t, %1; cvt.u32.u64 %0, t; }"
        : "=r"(a) : "l"(p));
    return a;
}
static __device__ __forceinline__ uint32_t sw128(uint32_t x) {
    return x ^ ((x >> 3) & 0x70);
}
__device__ __forceinline__ void cpa16(uint32_t s, const void* g) {
    asm volatile("cp.async.cg.shared.global [%0], [%1], 16;" :: "r"(s), "l"(g));
}
#define CP_COMMIT() asm volatile("cp.async.commit_group;" ::: "memory")
#define CP_WAIT1()  asm volatile("cp.async.wait_group 1;" ::: "memory")
#define CP_WAIT0()  asm volatile("cp.async.wait_group 0;" ::: "memory")

__device__ __forceinline__ void ldm4(uint32_t* r, uint32_t addr) {
    asm volatile("ldmatrix.sync.aligned.m8n8.x4.shared.b16 {%0,%1,%2,%3}, [%4];"
                 : "=r"(r[0]), "=r"(r[1]), "=r"(r[2]), "=r"(r[3]) : "r"(addr));
}
__device__ __forceinline__ void ldm4t(uint32_t* r, uint32_t addr) {
    asm volatile("ldmatrix.sync.aligned.m8n8.x4.trans.shared.b16 {%0,%1,%2,%3}, [%4];"
                 : "=r"(r[0]), "=r"(r[1]), "=r"(r[2]), "=r"(r[3]) : "r"(addr));
}
// bf16 MMA (attention)
__device__ __forceinline__ void mma16816(float* d, const uint32_t* a,
                                         uint32_t b0, uint32_t b1) {
    asm volatile(
        "mma.sync.aligned.m16n8k16.row.col.f32.bf16.bf16.f32 "
        "{%0,%1,%2,%3}, {%4,%5,%6,%7}, {%8,%9}, {%0,%1,%2,%3};"
        : "+f"(d[0]), "+f"(d[1]), "+f"(d[2]), "+f"(d[3])
        : "r"(a[0]), "r"(a[1]), "r"(a[2]), "r"(a[3]), "r"(b0), "r"(b1));
}
// fp16 MMA (GEMMs)
__device__ __forceinline__ void mma16816h(float* d, const uint32_t* a,
                                          uint32_t b0, uint32_t b1) {
    asm volatile(
        "mma.sync.aligned.m16n8k16.row.col.f32.f16.f16.f32 "
        "{%0,%1,%2,%3}, {%4,%5,%6,%7}, {%8,%9}, {%0,%1,%2,%3};"
        : "+f"(d[0]), "+f"(d[1]), "+f"(d[2]), "+f"(d[3])
        : "r"(a[0]), "r"(a[1]), "r"(a[2]), "r"(a[3]), "r"(b0), "r"(b1));
}
__device__ __forceinline__ uint32_t packbf(float a, float b) {
    __nv_bfloat162 t = __floats2bfloat162_rn(a, b);
    return *(uint32_t*)&t;
}
__device__ __forceinline__ uint32_t packhf(float a, float b) {
    __half2 t = __floats2half2_rn(a, b);
    return *(uint32_t*)&t;
}
__device__ __forceinline__ float ex2f(float x) {
    float r;
    asm("ex2.approx.f32 %0, %1;" : "=f"(r) : "f"(x));
    return r;
}

// ---------------------------------------------------------------------------
// Elementwise fp32 -> fp16 (hi, lo) split. n8 = elements/8.
// ---------------------------------------------------------------------------
__global__ void convert_hilo_h(const float* __restrict__ X,
                               __half* __restrict__ Hh,
                               __half* __restrict__ Hl, long n8)
{
    long i = (long)blockIdx.x * blockDim.x + threadIdx.x;
    if (i >= n8) return;
    float4 a = ((const float4*)X)[i * 2 + 0];
    float4 b = ((const float4*)X)[i * 2 + 1];
    float v[8] = {a.x, a.y, a.z, a.w, b.x, b.y, b.z, b.w};
    union { __half e[8]; uint4 u; } ph, pl;
#pragma unroll
    for (int j = 0; j < 8; j++) {
        __half h = __float2half(v[j]);
        ph.e[j] = h;
        pl.e[j] = __float2half(v[j] - __half2float(h));
    }
    ((uint4*)Hh)[i] = ph.u;
    ((uint4*)Hl)[i] = pl.u;
}

// ---------------------------------------------------------------------------
// Transpose + split: W[K,N] fp32 row-major -> Th/Tl [N,K] fp16 row-major
// ---------------------------------------------------------------------------
__global__ void wconv_h(const float* __restrict__ W, __half* __restrict__ Th,
                        __half* __restrict__ Tl, int K, int N)
{
    __shared__ float ts[32][33];
    int n0 = blockIdx.x * 32, k0 = blockIdx.y * 32;
    int tx = threadIdx.x, ty = threadIdx.y;
    for (int i = ty; i < 32; i += 8)
        ts[i][tx] = W[(size_t)(k0 + i) * N + n0 + tx];
    __syncthreads();
    for (int i = ty; i < 32; i += 8) {
        float v = ts[tx][i];
        __half h = __float2half(v);
        __half l = __float2half(v - __half2float(h));
        size_t o = (size_t)(n0 + i) * K + k0 + tx;
        Th[o] = h;
        Tl[o] = l;
    }
}

// ---------------------------------------------------------------------------
// GEMM config: CTA 128x128, 512 threads (16 warps, 4x4), warp tile 32x32,
// BK=64, 3-stage cp.async. fp16 operands; THREE selects 3-term (exact-ish)
// vs 2-term ((Ah+Al)*Bh, error ~2^-11) per CTA.
// ---------------------------------------------------------------------------
#define GEMM_THREADS 512
#define BKc 64
#define A_H_OFF 0
#define A_L_OFF 16384
#define B_H_OFF 32768
#define B_L_OFF 49152
#define STG_BYTES 65536
#define STAGES 3
#define GEMM_DSM (STAGES * STG_BYTES + 1024)

#define G3_MAINLOOP(K_, THREE)                                                 \
    const int nch = (K_) / BKc;                                                \
    auto load_stage = [&](int st, int k0) {                                    \
        uint32_t sbase = sb + st * STG_BYTES;                                  \
        _Pragma("unroll")                                                      \
        for (int rep = 0; rep < 2; rep++) {                                    \
            int i = tid + rep * GEMM_THREADS;                                  \
            int row = i >> 3, cc = i & 7;                                      \
            uint32_t so = sw128((uint32_t)(row * 128 + cc * 16));              \
            size_t ga = (size_t)(rowBase + row) * (K_) + k0 + cc * 8;          \
            size_t gb = (size_t)(colBase + row) * (K_) + k0 + cc * 8;          \
            cpa16(sbase + A_H_OFF + so, Ah + ga);                              \
            cpa16(sbase + A_L_OFF + so, Al + ga);                              \
            cpa16(sbase + B_H_OFF + so, Bh + gb);                              \
            cpa16(sbase + B_L_OFF + so, Bl + gb);                              \
        }                                                                      \
    };                                                                         \
    load_stage(0, 0); CP_COMMIT();                                             \
    load_stage(1, BKc); CP_COMMIT();                                           \
    float acc[2][4][4];                                                        \
    _Pragma("unroll")                                                          \
    for (int mi = 0; mi < 2; mi++)                                             \
        _Pragma("unroll")                                                      \
        for (int ni = 0; ni < 4; ni++)                                         \
            _Pragma("unroll")                                                  \
            for (int e = 0; e < 4; e++) acc[mi][ni][e] = 0.f;                  \
    const int lrow = lane & 15;                                                \
    const int lchunk = (lane >> 4) * 16;                                       \
    for (int c = 0; c < nch; c++) {                                            \
        CP_WAIT1();                                                            \
        __syncthreads();                                                       \
        int cn = c + STAGES - 1;                                               \
        if (cn < nch) load_stage(cn % STAGES, cn * BKc);                       \
        CP_COMMIT();                                                           \
        const uint32_t sbase = sb + (c % STAGES) * STG_BYTES;                  \
        _Pragma("unroll")                                                      \
        for (int ks = 0; ks < 4; ks++) {                                       \
            const int kb = ks * 32 + lchunk;                                   \
            uint32_t bh[2][4], bl[2][4];                                       \
            _Pragma("unroll")                                                  \
            for (int g = 0; g < 2; g++) {                                      \
                uint32_t bo = sw128((uint32_t)((wn + g * 16 + lrow) * 128 + kb)); \
                ldm4(bh[g], sbase + B_H_OFF + bo);                             \
                if (THREE) ldm4(bl[g], sbase + B_L_OFF + bo);                  \
            }                                                                  \
            _Pragma("unroll")                                                  \
            for (int mi = 0; mi < 2; mi++) {                                   \
                uint32_t ah[4], al[4];                                         \
                uint32_t ao = sw128((uint32_t)((wm + mi * 16 + lrow) * 128 + kb)); \
                ldm4(ah, sbase + A_H_OFF + ao);                                \
                ldm4(al, sbase + A_L_OFF + ao);                                \
                _Pragma("unroll")                                              \
                for (int ni = 0; ni < 4; ni++) {                               \
                    int g = ni >> 1, hf = ni & 1;                              \
                    mma16816h(acc[mi][ni], ah, bh[g][hf], bh[g][hf + 2]);      \
                    mma16816h(acc[mi][ni], al, bh[g][hf], bh[g][hf + 2]);      \
                    if (THREE)                                                 \
                        mma16816h(acc[mi][ni], ah, bl[g][hf], bl[g][hf + 2]);  \
                }                                                              \
            }                                                                  \
        }                                                                      \
    }

// ---------------------------------------------------------------------------
// GEMM #1: out = x @ w_qkv + b_qkv; q,k CTAs use 3-term fp16 (err 2^-22),
// v CTAs (colBase >= 2C) use 2-term (err ~2.8e-4, linear path to output).
// Epilogue: bias, RoPE (q,k), q scale, bf16 hi/lo split for attention.
// ---------------------------------------------------------------------------
__global__ __launch_bounds__(GEMM_THREADS, 1)
void gemm_qkv_rope(const __half* __restrict__ Ah,
                   const __half* __restrict__ Al,
                   const __half* __restrict__ Bh,
                   const __half* __restrict__ Bl,
                   const float* __restrict__ bias,
                   __nv_bfloat16* __restrict__ qh, __nv_bfloat16* __restrict__ ql,
                   __nv_bfloat16* __restrict__ kh, __nv_bfloat16* __restrict__ kl,
                   __nv_bfloat16* __restrict__ vh, __nv_bfloat16* __restrict__ vl)
{
    extern __shared__ char dsm[];
    const uint32_t raw = smem_u32(dsm);
    const uint32_t sb = (raw + 1023u) & ~1023u;

    const int tid = threadIdx.x;
    const int wid = tid >> 5, lane = tid & 31;
    const int wm = (wid & 3) * 32;
    const int wn = (wid >> 2) * 32;
    const int rowBase = blockIdx.y * 128;
    const int colBase = blockIdx.x * 128;
    const bool three = (colBase < 2 * C_);   // q,k: 3-term; v: 2-term

    G3_MAINLOOP(C_, three)

    const float QSC = 0.08838834764831845f * 1.4426950408889634f;
    const int gro = lane >> 2, thr = lane & 3;
#pragma unroll
    for (int mi = 0; mi < 2; mi++) {
        int r0 = rowBase + wm + mi * 16 + gro;
        int t0 = r0 & (T_ - 1), t1 = (r0 + 8) & (T_ - 1);
#pragma unroll
        for (int ni = 0; ni < 4; ni++) {
            int cb = colBase + wn + ni * 8 + thr * 2;   // even
            int sel = cb >> 11;          // 0=q, 1=k, 2=v
            int jj = cb & 2047;
            float bx = bias[cb], by = bias[cb + 1];
            float v00 = acc[mi][ni][0] + bx, v01 = acc[mi][ni][1] + by;
            float v10 = acc[mi][ni][2] + bx, v11 = acc[mi][ni][3] + by;
            if (sel < 2) {
                float e = (float)jj * (1.0f / (float)C_);
                float invf = expf(-9.210340371976184f * e);
                float ang = (float)t0 * invf;
                float kq = rintf(ang * 0.15915494309189535f);
                float rr = fmaf(-kq, 6.28318548202514648f, ang);
                rr = fmaf(-kq, -1.7484556000744083e-7f, rr);
                float s, c;
                __sincosf(rr, &s, &c);
                float o0 = v00 * c - v01 * s;
                float o1 = v00 * s + v01 * c;
                v00 = o0; v01 = o1;
                ang = (float)t1 * invf;
                kq = rintf(ang * 0.15915494309189535f);
                rr = fmaf(-kq, 6.28318548202514648f, ang);
                rr = fmaf(-kq, -1.7484556000744083e-7f, rr);
                __sincosf(rr, &s, &c);
                o0 = v10 * c - v11 * s;
                o1 = v10 * s + v11 * c;
                v10 = o0; v11 = o1;
                if (sel == 0) { v00 *= QSC; v01 *= QSC; v10 *= QSC; v11 *= QSC; }
            }
            __nv_bfloat16* oh = (sel == 0) ? qh : ((sel == 1) ? kh : vh);
            __nv_bfloat16* ol = (sel == 0) ? ql : ((sel == 1) ? kl : vl);
            size_t i0 = (size_t)r0 * C_ + jj;
            size_t i1 = (size_t)(r0 + 8) * C_ + jj;
            uint32_t h0 = packbf(v00, v01);
            __nv_bfloat162 hv0 = *(__nv_bfloat162*)&h0;
            uint32_t l0 = packbf(v00 - __bfloat162float(hv0.x),
                                 v01 - __bfloat162float(hv0.y));
            uint32_t h1 = packbf(v10, v11);
            __nv_bfloat162 hv1 = *(__nv_bfloat162*)&h1;
            uint32_t l1 = packbf(v10 - __bfloat162float(hv1.x),
                                 v11 - __bfloat162float(hv1.y));
            *(uint32_t*)(oh + i0) = h0;
            *(uint32_t*)(ol + i0) = l0;
            *(uint32_t*)(oh + i1) = h1;
            *(uint32_t*)(ol + i1) = l1;
        }
    }
}

// ---------------------------------------------------------------------------
// GEMM #2: out = y @ w_proj + b_proj (fp32 out), 2-term fp16.
// ---------------------------------------------------------------------------
__global__ __launch_bounds__(GEMM_THREADS, 1)
void gemm_proj(const __half* __restrict__ Ah,
               const __half* __restrict__ Al,
               const __half* __restrict__ Bh,
               const __half* __restrict__ Bl,
               const float* __restrict__ bias, float* __restrict__ Cm,
               int N, int K)
{
    extern __shared__ char dsm[];
    const uint32_t raw = smem_u32(dsm);
    const uint32_t sb = (raw + 1023u) & ~1023u;

    const int tid = threadIdx.x;
    const int wid = tid >> 5, lane = tid & 31;
    const int wm = (wid & 3) * 32;
    const int wn = (wid >> 2) * 32;
    const int rowBase = blockIdx.y * 128;
    const int colBase = blockIdx.x * 128;

    G3_MAINLOOP(K, false)

    const int gro = lane >> 2, thr = lane & 3;
#pragma unroll
    for (int mi = 0; mi < 2; mi++) {
        int r0 = rowBase + wm + mi * 16 + gro;
#pragma unroll
        for (int ni = 0; ni < 4; ni++) {
            int cb = colBase + wn + ni * 8 + thr * 2;
            float bx = bias[cb], by = bias[cb + 1];
            float2 o0, o1;
            o0.x = acc[mi][ni][0] + bx; o0.y = acc[mi][ni][1] + by;
            o1.x = acc[mi][ni][2] + bx; o1.y = acc[mi][ni][3] + by;
            *(float2*)(Cm + (size_t)r0 * N + cb) = o0;
            *(float2*)(Cm + (size_t)(r0 + 8) * N + cb) = o1;
        }
    }
}

// ---------------------------------------------------------------------------
// HMMA flash attention v3 (R12/R14-passing version; epilogue now packs y as
// fp16 hi/lo for the proj GEMM). 64 q-rows/CTA, 4 warps, Q in registers,
// 32-row KV tiles double-buffered via cp.async, 2 CTAs/SM.
// ---------------------------------------------------------------------------
#define QSTG 0
#define QSTG_L 16384
#define KV0 32768
#define KVSTB 32768
#define KH_O 0
#define KL_O 8192
#define VH_O 16384
#define VL_O 24576
#define ATTN3_DSM (32768 + 2 * 32768 + 1024)

__global__ __launch_bounds__(128, 2)
void attn_hmma3(const __nv_bfloat16* __restrict__ qh, const __nv_bfloat16* __restrict__ ql,
                const __nv_bfloat16* __restrict__ kh, const __nv_bfloat16* __restrict__ kl,
                const __nv_bfloat16* __restrict__ vh, const __nv_bfloat16* __restrict__ vl,
                __half* __restrict__ yh, __half* __restrict__ yl)
{
    extern __shared__ char asmem[];
    const uint32_t raw = smem_u32(asmem);
    const uint32_t sb = (raw + 1023u) & ~1023u;

    const int qt = blockIdx.x, h = blockIdx.y, b = blockIdx.z;
    const int qb = qt * 64;
    const int tid = threadIdx.x;
    const int wid = tid >> 5, lane = tid & 31;
    const int wq0 = wid * 16;
    const int lrow = lane & 15;
    const int lch = (lane >> 4) * 16;
    const int gro = lane >> 2, thr = lane & 3;
    const uint32_t rx = ((uint32_t)(lrow & 7)) << 4;

#pragma unroll
    for (int rep = 0; rep < 8; rep++) {
        int idx = tid + rep * 128;
        int row = idx >> 4, ch = idx & 15;
        uint32_t so = (uint32_t)row * 256 +
                      (((uint32_t)(ch * 16)) ^ (((uint32_t)(row & 7)) << 4));
        size_t g = ((size_t)(b * T_ + qb + row)) * C_ + h * DH + ch * 8;
        cpa16(sb + QSTG + so, qh + g);
        cpa16(sb + QSTG_L + so, ql + g);
    }
    CP_COMMIT();

    auto loadKV = [&](int st, int j2) {
        uint32_t stb = sb + KV0 + st * KVSTB;
        size_t grow = ((size_t)(b * T_ + j2 * 32)) * C_ + h * DH;
#pragma unroll
        for (int rep = 0; rep < 4; rep++) {
            int idx = tid + rep * 128;
            int row = idx >> 4, ch = idx & 15;
            uint32_t so = (uint32_t)row * 256 +
                          (((uint32_t)(ch * 16)) ^ (((uint32_t)(row & 7)) << 4));
            size_t g = grow + (size_t)row * C_ + ch * 8;
            cpa16(stb + KH_O + so, kh + g);
            cpa16(stb + KL_O + so, kl + g);
            cpa16(stb + VH_O + so, vh + g);
            cpa16(stb + VL_O + so, vl + g);
        }
    };

    loadKV(0, 0);
    CP_COMMIT();

    CP_WAIT1();
    __syncthreads();
    uint32_t aqh[8][4], aql[8][4];
#pragma unroll
    for (int kc = 0; kc < 8; kc++) {
        uint32_t off = (uint32_t)(wq0 + lrow) * 256 +
                       (((uint32_t)(kc * 32 + lch)) ^ rx);
        ldm4(aqh[kc], sb + QSTG + off);
        ldm4(aql[kc], sb + QSTG_L + off);
    }

    float m0 = -INFINITY, m1 = -INFINITY, l0 = 0.f, l1 = 0.f;
    float O[16][4];
#pragma unroll
    for (int i = 0; i < 16; i++)
#pragma unroll
        for (int e = 0; e < 4; e++) O[i][e] = 0.f;

    const int ntiles = 2 * qt + 2;
    for (int j = 0; j < ntiles; j++) {
        const int kvg = j * 32;
        if (j + 1 < ntiles) {
            loadKV((j + 1) & 1, j + 1);
            CP_COMMIT();
            CP_WAIT1();
        } else {
            CP_WAIT0();
        }
        __syncthreads();

        const uint32_t stb = sb + KV0 + (j & 1) * KVSTB;
        const uint32_t sKH = stb + KH_O, sKL = stb + KL_O;
        const uint32_t sVH = stb + VH_O, sVL = stb + VL_O;

        float c[4][4];
#pragma unroll
        for (int nt = 0; nt < 4; nt++)
#pragma unroll
            for (int e = 0; e < 4; e++) c[nt][e] = 0.f;

#pragma unroll
        for (int kc = 0; kc < 8; kc++) {
            const uint32_t kb = (uint32_t)(kc * 32 + lch);
#pragma unroll
            for (int g4 = 0; g4 < 2; g4++) {
                uint32_t off = (uint32_t)(g4 * 16 + lrow) * 256 + (kb ^ rx);
                uint32_t bh[4], bl[4];
                ldm4(bh, sKH + off);
                ldm4(bl, sKL + off);
#pragma unroll
                for (int hf = 0; hf < 2; hf++) {
                    int nt = g4 * 2 + hf;
                    mma16816(c[nt], aqh[kc], bh[hf], bh[hf + 2]);
                    mma16816(c[nt], aqh[kc], bl[hf], bl[hf + 2]);
                    mma16816(c[nt], aql[kc], bh[hf], bh[hf + 2]);
                }
            }
        }

        const int row_lo = qb + wq0 + gro;
        const int row_hi = row_lo + 8;
        if (kvg + 31 > qb + wq0) {
#pragma unroll
            for (int nt = 0; nt < 4; nt++) {
                int cbase = kvg + nt * 8 + 2 * thr;
                if (cbase > row_lo)     c[nt][0] = -1e30f;
                if (cbase + 1 > row_lo) c[nt][1] = -1e30f;
                if (cbase > row_hi)     c[nt][2] = -1e30f;
                if (cbase + 1 > row_hi) c[nt][3] = -1e30f;
            }
        }

        float mt0 = -1e30f, mt1 = -1e30f;
#pragma unroll
        for (int nt = 0; nt < 4; nt++) {
            mt0 = fmaxf(mt0, fmaxf(c[nt][0], c[nt][1]));
            mt1 = fmaxf(mt1, fmaxf(c[nt][2], c[nt][3]));
        }
        mt0 = fmaxf(mt0, __shfl_xor_sync(0xffffffffu, mt0, 1));
        mt0 = fmaxf(mt0, __shfl_xor_sync(0xffffffffu, mt0, 2));
        mt1 = fmaxf(mt1, __shfl_xor_sync(0xffffffffu, mt1, 1));
        mt1 = fmaxf(mt1, __shfl_xor_sync(0xffffffffu, mt1, 2));
        float mn0 = fmaxf(m0, mt0), mn1 = fmaxf(m1, mt1);
        float cor0 = ex2f(m0 - mn0), cor1 = ex2f(m1 - mn1);
        float s0 = 0.f, s1 = 0.f;
#pragma unroll
        for (int nt = 0; nt < 4; nt++) {
            c[nt][0] = ex2f(c[nt][0] - mn0); s0 += c[nt][0];
            c[nt][1] = ex2f(c[nt][1] - mn0); s0 += c[nt][1];
            c[nt][2] = ex2f(c[nt][2] - mn1); s1 += c[nt][2];
            c[nt][3] = ex2f(c[nt][3] - mn1); s1 += c[nt][3];
        }
        s0 += __shfl_xor_sync(0xffffffffu, s0, 1);
        s0 += __shfl_xor_sync(0xffffffffu, s0, 2);
        s1 += __shfl_xor_sync(0xffffffffu, s1, 1);
        s1 += __shfl_xor_sync(0xffffffffu, s1, 2);
        l0 = l0 * cor0 + s0; m0 = mn0;
        l1 = l1 * cor1 + s1; m1 = mn1;
#pragma unroll
        for (int i = 0; i < 16; i++) {
            O[i][0] *= cor0; O[i][1] *= cor0;
            O[i][2] *= cor1; O[i][3] *= cor1;
        }

        const uint32_t rxv = ((uint32_t)(lane & 7)) << 4;
        const uint32_t colb = (uint32_t)((lane >> 3) & 1) * 16;
#pragma unroll
        for (int kc2 = 0; kc2 < 2; kc2++) {
            uint32_t aph[4], apl[4];
            {
                float p00 = c[2 * kc2][0], p01 = c[2 * kc2][1];
                float p10 = c[2 * kc2][2], p11 = c[2 * kc2][3];
                float p20 = c[2 * kc2 + 1][0], p21 = c[2 * kc2 + 1][1];
                float p30 = c[2 * kc2 + 1][2], p31 = c[2 * kc2 + 1][3];
                aph[0] = packbf(p00, p01);
                aph[1] = packbf(p10, p11);
                aph[2] = packbf(p20, p21);
                aph[3] = packbf(p30, p31);
                __nv_bfloat162* t;
                t = (__nv_bfloat162*)&aph[0];
                apl[0] = packbf(p00 - __bfloat162float(t->x), p01 - __bfloat162float(t->y));
                t = (__nv_bfloat162*)&aph[1];
                apl[1] = packbf(p10 - __bfloat162float(t->x), p11 - __bfloat162float(t->y));
                t = (__nv_bfloat162*)&aph[2];
                apl[2] = packbf(p20 - __bfloat162float(t->x), p21 - __bfloat162float(t->y));
                t = (__nv_bfloat162*)&aph[3];
                apl[3] = packbf(p30 - __bfloat162float(t->x), p31 - __bfloat162float(t->y));
            }
            const uint32_t vrow = (uint32_t)(kc2 * 16 + (lane & 7) + (lane >> 4) * 8);
#pragma unroll
            for (int gg = 0; gg < 8; gg++) {
                uint32_t off = vrow * 256 + (((uint32_t)(gg * 32) + colb) ^ rxv);
                uint32_t vhf[4], vlf[4];
                ldm4t(vhf, sVH + off);
                ldm4t(vlf, sVL + off);
#pragma unroll
                for (int hf = 0; hf < 2; hf++) {
                    int nt2 = gg * 2 + hf;
                    mma16816(O[nt2], aph, vhf[hf], vhf[hf + 2]);
                    mma16816(O[nt2], aph, vlf[hf], vlf[hf + 2]);
                    mma16816(O[nt2], apl, vhf[hf], vhf[hf + 2]);
                }
            }
        }
        __syncthreads();
    }

    // ---- Epilogue: normalize, split fp16 hi/lo, store y for proj GEMM ----
    const float il0 = 1.f / l0, il1 = 1.f / l1;
    const int row_lo = qb + wq0 + gro;
    size_t r0o = (size_t)(b * T_ + row_lo) * C_;
    size_t r1o = (size_t)(b * T_ + row_lo + 8) * C_;
#pragma unroll
    for (int nt2 = 0; nt2 < 16; nt2++) {
        int col = h * DH + nt2 * 8 + 2 * thr;
        float a0 = O[nt2][0] * il0, a1 = O[nt2][1] * il0;
        float b0 = O[nt2][2] * il1, b1 = O[nt2][3] * il1;
        uint32_t h0 = packhf(a0, a1);
        __half2 hv0 = *(__half2*)&h0;
        uint32_t l0w = packhf(a0 - __half2float(hv0.x), a1 - __half2float(hv0.y));
        uint32_t h1 = packhf(b0, b1);
        __half2 hv1 = *(__half2*)&h1;
        uint32_t l1w = packhf(b0 - __half2float(hv1.x), b1 - __half2float(hv1.y));
        *(uint32_t*)(yh + r0o + col) = h0;
        *(uint32_t*)(yl + r0o + col) = l0w;
        *(uint32_t*)(yh + r1o + col) = h1;
        *(uint32_t*)(yl + r1o + col) = l1w;
    }
}

// ---------------------------------------------------------------------------
// Launch
// ---------------------------------------------------------------------------
extern "C" void kernel_launch(void* const* d_in, const int* in_sizes, int n_in,
                              void* d_out, int out_size)
{
    (void)in_sizes; (void)n_in; (void)out_size;
    const float* x      = (const float*)d_in[0];
    const float* w_qkv  = (const float*)d_in[1];
    const float* b_qkv  = (const float*)d_in[2];
    const float* w_proj = (const float*)d_in[3];
    const float* b_proj = (const float*)d_in[4];
    float* out = (float*)d_out;

    void *p_xh, *p_xl, *p_yh, *p_yl, *p_wqh, *p_wql, *p_wph, *p_wpl;
    void *p_qh, *p_ql, *p_kh, *p_kl, *p_vh, *p_vl;
    cudaGetSymbolAddress(&p_xh, g_xc_h);
    cudaGetSymbolAddress(&p_xl, g_xc_l);
    cudaGetSymbolAddress(&p_yh, g_yc_h);
    cudaGetSymbolAddress(&p_yl, g_yc_l);
    cudaGetSymbolAddress(&p_wqh, g_wq_h);
    cudaGetSymbolAddress(&p_wql, g_wq_l);
    cudaGetSymbolAddress(&p_wph, g_wp_h);
    cudaGetSymbolAddress(&p_wpl, g_wp_l);
    cudaGetSymbolAddress(&p_qh, g_qh);
    cudaGetSymbolAddress(&p_ql, g_ql);
    cudaGetSymbolAddress(&p_kh, g_kh);
    cudaGetSymbolAddress(&p_kl, g_kl);
    cudaGetSymbolAddress(&p_vh, g_vh);
    cudaGetSymbolAddress(&p_vl, g_vl);

    cudaFuncSetAttribute(gemm_qkv_rope,
                         cudaFuncAttributeMaxDynamicSharedMemorySize, GEMM_DSM);
    cudaFuncSetAttribute(gemm_proj,
                         cudaFuncAttributeMaxDynamicSharedMemorySize, GEMM_DSM);
    cudaFuncSetAttribute(attn_hmma3,
                         cudaFuncAttributeMaxDynamicSharedMemorySize, ATTN3_DSM);

    // 0) Weight transpose+split and x split (fp16 hi/lo)
    wconv_h<<<dim3(THREE_C / 32, C_ / 32), dim3(32, 8)>>>(
        w_qkv, (__half*)p_wqh, (__half*)p_wql, C_, THREE_C);
    wconv_h<<<dim3(C_ / 32, C_ / 32), dim3(32, 8)>>>(
        w_proj, (__half*)p_wph, (__half*)p_wpl, C_, C_);
    {
        long n8 = (long)M_ * C_ / 8;
        convert_hilo_h<<<(int)((n8 + 255) / 256), 256>>>(
            x, (__half*)p_xh, (__half*)p_xl, n8);
    }

    // 1) QKV GEMM (fp16; q,k 3-term, v 2-term) + bias + RoPE + split
    gemm_qkv_rope<<<dim3(THREE_C / 128, M_ / 128), GEMM_THREADS, GEMM_DSM>>>(
        (const __half*)p_xh, (const __half*)p_xl,
        (const __half*)p_wqh, (const __half*)p_wql,
        b_qkv,
        (__nv_bfloat16*)p_qh, (__nv_bfloat16*)p_ql,
        (__nv_bfloat16*)p_kh, (__nv_bfloat16*)p_kl,
        (__nv_bfloat16*)p_vh, (__nv_bfloat16*)p_vl);

    // 2) Causal flash attention (bf16x3 HMMA, 2 CTA/SM) -> y fp16 hi/lo
    {
        dim3 grid(T_ / 64, H_, B_);
        attn_hmma3<<<grid, 128, ATTN3_DSM>>>(
            (const __nv_bfloat16*)p_qh, (const __nv_bfloat16*)p_ql,
            (const __nv_bfloat16*)p_kh, (const __nv_bfloat16*)p_kl,
            (const __nv_bfloat16*)p_vh, (const __nv_bfloat16*)p_vl,
            (__half*)p_yh, (__half*)p_yl);
    }

    // 3) out = y @ w_proj + b_proj (fp16 2-term, fp32 out)
    gemm_proj<<<dim3(C_ / 128, M_ / 128), GEMM_THREADS, GEMM_DSM>>>(
        (const __half*)p_yh, (const __half*)p_yl,
        (const __half*)p_wph, (const __half*)p_wpl,
        b_proj, out, C_, C_);
}

// round 16
// speedup vs baseline: 2.3675x; 1.3182x over previous
#include <cuda_runtime.h>
#include <cuda_bf16.h>
#include <cuda_fp16.h>
#include <math.h>
#include <stdint.h>

// Problem constants
#define B_ 4
#define T_ 2048
#define C_ 2048
#define H_ 16
#define DH 128
#define THREE_C (3 * C_)
#define M_ (B_ * T_)   // 8192

// ---------------------------------------------------------------------------
// Device-global scratch (allocation-free)
// ---------------------------------------------------------------------------
__device__ __half g_xc_h[(size_t)M_ * C_];
__device__ __half g_xc_l[(size_t)M_ * C_];
__device__ __half g_yc_h[(size_t)M_ * C_];
__device__ __half g_yc_l[(size_t)M_ * C_];
__device__ __half g_wq_h[(size_t)THREE_C * C_];      // w_qkv^T [6144,2048]
__device__ __half g_wq_l[(size_t)THREE_C * C_];
__device__ __half g_wp_h[(size_t)C_ * C_];           // w_proj^T [2048,2048]
__device__ __half g_wp_l[(size_t)C_ * C_];
// Roped/scaled fp16 Q (hi/lo) and K,V (hi only), layout [M_][C_] (c=h*128+d)
__device__ __half g_qh[(size_t)M_ * C_];
__device__ __half g_ql[(size_t)M_ * C_];
__device__ __half g_kh[(size_t)M_ * C_];
__device__ __half g_vh[(size_t)M_ * C_];

// ---------------------------------------------------------------------------
// Helpers
// ---------------------------------------------------------------------------
__device__ __forceinline__ uint32_t smem_u32(const void* p) {
    uint32_t a;
    asm("{ .reg .u64 t; cvta.to.shared.u64 t, %1; cvt.u32.u64 %0, t; }"
        : "=r"(a) : "l"(p));
    return a;
}
static __device__ __forceinline__ uint32_t sw128(uint32_t x) {
    return x ^ ((x >> 3) & 0x70);
}
__device__ __forceinline__ void cpa16(uint32_t s, const void* g) {
    asm volatile("cp.async.cg.shared.global [%0], [%1], 16;" :: "r"(s), "l"(g));
}
#define CP_COMMIT() asm volatile("cp.async.commit_group;" ::: "memory")
#define CP_WAIT1()  asm volatile("cp.async.wait_group 1;" ::: "memory")
#define CP_WAIT0()  asm volatile("cp.async.wait_group 0;" ::: "memory")

__device__ __forceinline__ void ldm4(uint32_t* r, uint32_t addr) {
    asm volatile("ldmatrix.sync.aligned.m8n8.x4.shared.b16 {%0,%1,%2,%3}, [%4];"
                 : "=r"(r[0]), "=r"(r[1]), "=r"(r[2]), "=r"(r[3]) : "r"(addr));
}
__device__ __forceinline__ void ldm4t(uint32_t* r, uint32_t addr) {
    asm volatile("ldmatrix.sync.aligned.m8n8.x4.trans.shared.b16 {%0,%1,%2,%3}, [%4];"
                 : "=r"(r[0]), "=r"(r[1]), "=r"(r[2]), "=r"(r[3]) : "r"(addr));
}
// fp16 MMA
__device__ __forceinline__ void mma16816h(float* d, const uint32_t* a,
                                          uint32_t b0, uint32_t b1) {
    asm volatile(
        "mma.sync.aligned.m16n8k16.row.col.f32.f16.f16.f32 "
        "{%0,%1,%2,%3}, {%4,%5,%6,%7}, {%8,%9}, {%0,%1,%2,%3};"
        : "+f"(d[0]), "+f"(d[1]), "+f"(d[2]), "+f"(d[3])
        : "r"(a[0]), "r"(a[1]), "r"(a[2]), "r"(a[3]), "r"(b0), "r"(b1));
}
__device__ __forceinline__ uint32_t packhf(float a, float b) {
    __half2 t = __floats2half2_rn(a, b);   // .x = a (low 16 bits)
    return *(uint32_t*)&t;
}
__device__ __forceinline__ float ex2f(float x) {
    float r;
    asm("ex2.approx.f32 %0, %1;" : "=f"(r) : "f"(x));
    return r;
}

// ---------------------------------------------------------------------------
// Elementwise fp32 -> fp16 (hi, lo) split. n8 = elements/8.
// ---------------------------------------------------------------------------
__global__ void convert_hilo_h(const float* __restrict__ X,
                               __half* __restrict__ Hh,
                               __half* __restrict__ Hl, long n8)
{
    long i = (long)blockIdx.x * blockDim.x + threadIdx.x;
    if (i >= n8) return;
    float4 a = ((const float4*)X)[i * 2 + 0];
    float4 b = ((const float4*)X)[i * 2 + 1];
    float v[8] = {a.x, a.y, a.z, a.w, b.x, b.y, b.z, b.w};
    union { __half e[8]; uint4 u; } ph, pl;
#pragma unroll
    for (int j = 0; j < 8; j++) {
        __half h = __float2half(v[j]);
        ph.e[j] = h;
        pl.e[j] = __float2half(v[j] - __half2float(h));
    }
    ((uint4*)Hh)[i] = ph.u;
    ((uint4*)Hl)[i] = pl.u;
}

// ---------------------------------------------------------------------------
// Transpose (hi only needed for B operands): W[K,N] fp32 -> Th [N,K] fp16
// ---------------------------------------------------------------------------
__global__ void wconv_h(const float* __restrict__ W, __half* __restrict__ Th,
                        int K, int N)
{
    __shared__ float ts[32][33];
    int n0 = blockIdx.x * 32, k0 = blockIdx.y * 32;
    int tx = threadIdx.x, ty = threadIdx.y;
    for (int i = ty; i < 32; i += 8)
        ts[i][tx] = W[(size_t)(k0 + i) * N + n0 + tx];
    __syncthreads();
    for (int i = ty; i < 32; i += 8) {
        float v = ts[tx][i];
        Th[(size_t)(n0 + i) * K + k0 + tx] = __float2half(v);
    }
}

// ---------------------------------------------------------------------------
// GEMM: CTA 128x128, 512 threads (16 warps, 4x4), warp tile 32x32, BK=64,
// 3-stage cp.async. 2-term fp16: D = (Ah+Al) * Bh. Stage = 48KB.
// ---------------------------------------------------------------------------
#define GEMM_THREADS 512
#define BKc 64
#define A_H_OFF 0
#define A_L_OFF 16384
#define B_H_OFF 32768
#define STG_BYTES 49152
#define STAGES 3
#define GEMM_DSM (STAGES * STG_BYTES + 1024)

#define G3_MAINLOOP(K_)                                                        \
    const int nch = (K_) / BKc;                                                \
    auto load_stage = [&](int st, int k0) {                                    \
        uint32_t sbase = sb + st * STG_BYTES;                                  \
        _Pragma("unroll")                                                      \
        for (int rep = 0; rep < 2; rep++) {                                    \
            int i = tid + rep * GEMM_THREADS;                                  \
            int row = i >> 3, cc = i & 7;                                      \
            uint32_t so = sw128((uint32_t)(row * 128 + cc * 16));              \
            size_t ga = (size_t)(rowBase + row) * (K_) + k0 + cc * 8;          \
            size_t gb = (size_t)(colBase + row) * (K_) + k0 + cc * 8;          \
            cpa16(sbase + A_H_OFF + so, Ah + ga);                              \
            cpa16(sbase + A_L_OFF + so, Al + ga);                              \
            cpa16(sbase + B_H_OFF + so, Bh + gb);                              \
        }                                                                      \
    };                                                                         \
    load_stage(0, 0); CP_COMMIT();                                             \
    load_stage(1, BKc); CP_COMMIT();                                           \
    float acc[2][4][4];                                                        \
    _Pragma("unroll")                                                          \
    for (int mi = 0; mi < 2; mi++)                                             \
        _Pragma("unroll")                                                      \
        for (int ni = 0; ni < 4; ni++)                                         \
            _Pragma("unroll")                                                  \
            for (int e = 0; e < 4; e++) acc[mi][ni][e] = 0.f;                  \
    const int lrow = lane & 15;                                                \
    const int lchunk = (lane >> 4) * 16;                                       \
    for (int c = 0; c < nch; c++) {                                            \
        CP_WAIT1();                                                            \
        __syncthreads();                                                       \
        int cn = c + STAGES - 1;                                               \
        if (cn < nch) load_stage(cn % STAGES, cn * BKc);                       \
        CP_COMMIT();                                                           \
        const uint32_t sbase = sb + (c % STAGES) * STG_BYTES;                  \
        _Pragma("unroll")                                                      \
        for (int ks = 0; ks < 4; ks++) {                                       \
            const int kb = ks * 32 + lchunk;                                   \
            uint32_t bh[2][4];                                                 \
            _Pragma("unroll")                                                  \
            for (int g = 0; g < 2; g++) {                                      \
                uint32_t bo = sw128((uint32_t)((wn + g * 16 + lrow) * 128 + kb)); \
                ldm4(bh[g], sbase + B_H_OFF + bo);                             \
            }                                                                  \
            _Pragma("unroll")                                                  \
            for (int mi = 0; mi < 2; mi++) {                                   \
                uint32_t ah[4], al[4];                                         \
                uint32_t ao = sw128((uint32_t)((wm + mi * 16 + lrow) * 128 + kb)); \
                ldm4(ah, sbase + A_H_OFF + ao);                                \
                ldm4(al, sbase + A_L_OFF + ao);                                \
                _Pragma("unroll")                                              \
                for (int ni = 0; ni < 4; ni++) {                               \
                    int g = ni >> 1, hf = ni & 1;                              \
                    mma16816h(acc[mi][ni], ah, bh[g][hf], bh[g][hf + 2]);      \
                    mma16816h(acc[mi][ni], al, bh[g][hf], bh[g][hf + 2]);      \
                }                                                              \
            }                                                                  \
        }                                                                      \
    }

// ---------------------------------------------------------------------------
// GEMM #1: out = x @ w_qkv + b_qkv (2-term fp16).
// Epilogue: bias, RoPE (q,k), q scale; q -> fp16 hi/lo; k,v -> fp16 hi only.
// ---------------------------------------------------------------------------
__global__ __launch_bounds__(GEMM_THREADS, 1)
void gemm_qkv_rope(const __half* __restrict__ Ah,
                   const __half* __restrict__ Al,
                   const __half* __restrict__ Bh,
                   const float* __restrict__ bias,
                   __half* __restrict__ qh, __half* __restrict__ ql,
                   __half* __restrict__ kh, __half* __restrict__ vh)
{
    extern __shared__ char dsm[];
    const uint32_t raw = smem_u32(dsm);
    const uint32_t sb = (raw + 1023u) & ~1023u;

    const int tid = threadIdx.x;
    const int wid = tid >> 5, lane = tid & 31;
    const int wm = (wid & 3) * 32;
    const int wn = (wid >> 2) * 32;
    const int rowBase = blockIdx.y * 128;
    const int colBase = blockIdx.x * 128;

    G3_MAINLOOP(C_)

    const float QSC = 0.08838834764831845f * 1.4426950408889634f;
    const int gro = lane >> 2, thr = lane & 3;
#pragma unroll
    for (int mi = 0; mi < 2; mi++) {
        int r0 = rowBase + wm + mi * 16 + gro;
        int t0 = r0 & (T_ - 1), t1 = (r0 + 8) & (T_ - 1);
#pragma unroll
        for (int ni = 0; ni < 4; ni++) {
            int cb = colBase + wn + ni * 8 + thr * 2;   // even
            int sel = cb >> 11;          // 0=q, 1=k, 2=v
            int jj = cb & 2047;
            float bx = bias[cb], by = bias[cb + 1];
            float v00 = acc[mi][ni][0] + bx, v01 = acc[mi][ni][1] + by;
            float v10 = acc[mi][ni][2] + bx, v11 = acc[mi][ni][3] + by;
            if (sel < 2) {
                float e = (float)jj * (1.0f / (float)C_);
                float invf = expf(-9.210340371976184f * e);
                float ang = (float)t0 * invf;
                float kq = rintf(ang * 0.15915494309189535f);
                float rr = fmaf(-kq, 6.28318548202514648f, ang);
                rr = fmaf(-kq, -1.7484556000744083e-7f, rr);
                float s, c;
                __sincosf(rr, &s, &c);
                float o0 = v00 * c - v01 * s;
                float o1 = v00 * s + v01 * c;
                v00 = o0; v01 = o1;
                ang = (float)t1 * invf;
                kq = rintf(ang * 0.15915494309189535f);
                rr = fmaf(-kq, 6.28318548202514648f, ang);
                rr = fmaf(-kq, -1.7484556000744083e-7f, rr);
                __sincosf(rr, &s, &c);
                o0 = v10 * c - v11 * s;
                o1 = v10 * s + v11 * c;
                v10 = o0; v11 = o1;
            }
            size_t i0 = (size_t)r0 * C_ + jj;
            size_t i1 = (size_t)(r0 + 8) * C_ + jj;
            if (sel == 0) {
                v00 *= QSC; v01 *= QSC; v10 *= QSC; v11 *= QSC;
                uint32_t h0 = packhf(v00, v01);
                __half2 hv0 = *(__half2*)&h0;
                uint32_t l0 = packhf(v00 - __half2float(hv0.x),
                                     v01 - __half2float(hv0.y));
                uint32_t h1 = packhf(v10, v11);
                __half2 hv1 = *(__half2*)&h1;
                uint32_t l1 = packhf(v10 - __half2float(hv1.x),
                                     v11 - __half2float(hv1.y));
                *(uint32_t*)(qh + i0) = h0;
                *(uint32_t*)(ql + i0) = l0;
                *(uint32_t*)(qh + i1) = h1;
                *(uint32_t*)(ql + i1) = l1;
            } else {
                __half* dst = (sel == 1) ? kh : vh;
                *(uint32_t*)(dst + i0) = packhf(v00, v01);
                *(uint32_t*)(dst + i1) = packhf(v10, v11);
            }
        }
    }
}

// ---------------------------------------------------------------------------
// GEMM #2: out = y @ w_proj + b_proj (fp32 out), 2-term fp16.
// ---------------------------------------------------------------------------
__global__ __launch_bounds__(GEMM_THREADS, 1)
void gemm_proj(const __half* __restrict__ Ah,
               const __half* __restrict__ Al,
               const __half* __restrict__ Bh,
               const float* __restrict__ bias, float* __restrict__ Cm,
               int N, int K)
{
    extern __shared__ char dsm[];
    const uint32_t raw = smem_u32(dsm);
    const uint32_t sb = (raw + 1023u) & ~1023u;

    const int tid = threadIdx.x;
    const int wid = tid >> 5, lane = tid & 31;
    const int wm = (wid & 3) * 32;
    const int wn = (wid >> 2) * 32;
    const int rowBase = blockIdx.y * 128;
    const int colBase = blockIdx.x * 128;

    G3_MAINLOOP(K)

    const int gro = lane >> 2, thr = lane & 3;
#pragma unroll
    for (int mi = 0; mi < 2; mi++) {
        int r0 = rowBase + wm + mi * 16 + gro;
#pragma unroll
        for (int ni = 0; ni < 4; ni++) {
            int cb = colBase + wn + ni * 8 + thr * 2;
            float bx = bias[cb], by = bias[cb + 1];
            float2 o0, o1;
            o0.x = acc[mi][ni][0] + bx; o0.y = acc[mi][ni][1] + by;
            o1.x = acc[mi][ni][2] + bx; o1.y = acc[mi][ni][3] + by;
            *(float2*)(Cm + (size_t)r0 * N + cb) = o0;
            *(float2*)(Cm + (size_t)(r0 + 8) * N + cb) = o1;
        }
    }
}

// ---------------------------------------------------------------------------
// fp16 flash attention: S = (Qh+Ql)*Kh (2 MMA), O += (Ph+Pl)*Vh (2 MMA).
// K,V hi-only => half the KV traffic. 64 q-rows/CTA, 4 warps, Q in regs,
// 32-row KV tiles double-buffered via cp.async, 2 CTAs/SM.
// SMEM: Q hi 16KB @0, Q lo 16KB @16384; 2 KV stages 16KB (KH 8KB, VH 8KB).
// ---------------------------------------------------------------------------
#define QSTG 0
#define QSTG_L 16384
#define KV0 32768
#define KVSTB 16384
#define KH_O 0
#define VH_O 8192
#define ATTN3_DSM (32768 + 2 * 16384 + 1024)

__global__ __launch_bounds__(128, 2)
void attn_hmma4(const __half* __restrict__ qh, const __half* __restrict__ ql,
                const __half* __restrict__ kh, const __half* __restrict__ vh,
                __half* __restrict__ yh, __half* __restrict__ yl)
{
    extern __shared__ char asmem[];
    const uint32_t raw = smem_u32(asmem);
    const uint32_t sb = (raw + 1023u) & ~1023u;

    const int qt = blockIdx.x, h = blockIdx.y, b = blockIdx.z;
    const int qb = qt * 64;
    const int tid = threadIdx.x;
    const int wid = tid >> 5, lane = tid & 31;
    const int wq0 = wid * 16;
    const int lrow = lane & 15;
    const int lch = (lane >> 4) * 16;
    const int gro = lane >> 2, thr = lane & 3;
    const uint32_t rx = ((uint32_t)(lrow & 7)) << 4;

    // ---- Stage Q tile (hi+lo) via cp.async ----
#pragma unroll
    for (int rep = 0; rep < 8; rep++) {
        int idx = tid + rep * 128;
        int row = idx >> 4, ch = idx & 15;
        uint32_t so = (uint32_t)row * 256 +
                      (((uint32_t)(ch * 16)) ^ (((uint32_t)(row & 7)) << 4));
        size_t g = ((size_t)(b * T_ + qb + row)) * C_ + h * DH + ch * 8;
        cpa16(sb + QSTG + so, qh + g);
        cpa16(sb + QSTG_L + so, ql + g);
    }
    CP_COMMIT();

    auto loadKV = [&](int st, int j2) {
        uint32_t stb = sb + KV0 + st * KVSTB;
        size_t grow = ((size_t)(b * T_ + j2 * 32)) * C_ + h * DH;
#pragma unroll
        for (int rep = 0; rep < 4; rep++) {
            int idx = tid + rep * 128;
            int row = idx >> 4, ch = idx & 15;
            uint32_t so = (uint32_t)row * 256 +
                          (((uint32_t)(ch * 16)) ^ (((uint32_t)(row & 7)) << 4));
            size_t g = grow + (size_t)row * C_ + ch * 8;
            cpa16(stb + KH_O + so, kh + g);
            cpa16(stb + VH_O + so, vh + g);
        }
    };

    loadKV(0, 0);
    CP_COMMIT();

    CP_WAIT1();
    __syncthreads();
    uint32_t aqh[8][4], aql[8][4];
#pragma unroll
    for (int kc = 0; kc < 8; kc++) {
        uint32_t off = (uint32_t)(wq0 + lrow) * 256 +
                       (((uint32_t)(kc * 32 + lch)) ^ rx);
        ldm4(aqh[kc], sb + QSTG + off);
        ldm4(aql[kc], sb + QSTG_L + off);
    }

    float m0 = -INFINITY, m1 = -INFINITY, l0 = 0.f, l1 = 0.f;
    float O[16][4];
#pragma unroll
    for (int i = 0; i < 16; i++)
#pragma unroll
        for (int e = 0; e < 4; e++) O[i][e] = 0.f;

    const int ntiles = 2 * qt + 2;
    for (int j = 0; j < ntiles; j++) {
        const int kvg = j * 32;
        if (j + 1 < ntiles) {
            loadKV((j + 1) & 1, j + 1);
            CP_COMMIT();
            CP_WAIT1();
        } else {
            CP_WAIT0();
        }
        __syncthreads();

        const uint32_t stb = sb + KV0 + (j & 1) * KVSTB;
        const uint32_t sKH = stb + KH_O;
        const uint32_t sVH = stb + VH_O;

        // ---- S = (Qh+Ql) Kh^T, in log2 domain ----
        float c[4][4];
#pragma unroll
        for (int nt = 0; nt < 4; nt++)
#pragma unroll
            for (int e = 0; e < 4; e++) c[nt][e] = 0.f;

#pragma unroll
        for (int kc = 0; kc < 8; kc++) {
            const uint32_t kb = (uint32_t)(kc * 32 + lch);
#pragma unroll
            for (int g4 = 0; g4 < 2; g4++) {
                uint32_t off = (uint32_t)(g4 * 16 + lrow) * 256 + (kb ^ rx);
                uint32_t bh[4];
                ldm4(bh, sKH + off);
#pragma unroll
                for (int hf = 0; hf < 2; hf++) {
                    int nt = g4 * 2 + hf;
                    mma16816h(c[nt], aqh[kc], bh[hf], bh[hf + 2]);
                    mma16816h(c[nt], aql[kc], bh[hf], bh[hf + 2]);
                }
            }
        }

        // ---- Causal mask ----
        const int row_lo = qb + wq0 + gro;
        const int row_hi = row_lo + 8;
        if (kvg + 31 > qb + wq0) {
#pragma unroll
            for (int nt = 0; nt < 4; nt++) {
                int cbase = kvg + nt * 8 + 2 * thr;
                if (cbase > row_lo)     c[nt][0] = -1e30f;
                if (cbase + 1 > row_lo) c[nt][1] = -1e30f;
                if (cbase > row_hi)     c[nt][2] = -1e30f;
                if (cbase + 1 > row_hi) c[nt][3] = -1e30f;
            }
        }

        // ---- Online softmax (base-2) ----
        float mt0 = -1e30f, mt1 = -1e30f;
#pragma unroll
        for (int nt = 0; nt < 4; nt++) {
            mt0 = fmaxf(mt0, fmaxf(c[nt][0], c[nt][1]));
            mt1 = fmaxf(mt1, fmaxf(c[nt][2], c[nt][3]));
        }
        mt0 = fmaxf(mt0, __shfl_xor_sync(0xffffffffu, mt0, 1));
        mt0 = fmaxf(mt0, __shfl_xor_sync(0xffffffffu, mt0, 2));
        mt1 = fmaxf(mt1, __shfl_xor_sync(0xffffffffu, mt1, 1));
        mt1 = fmaxf(mt1, __shfl_xor_sync(0xffffffffu, mt1, 2));
        float mn0 = fmaxf(m0, mt0), mn1 = fmaxf(m1, mt1);
        float cor0 = ex2f(m0 - mn0), cor1 = ex2f(m1 - mn1);
        float s0 = 0.f, s1 = 0.f;
#pragma unroll
        for (int nt = 0; nt < 4; nt++) {
            c[nt][0] = ex2f(c[nt][0] - mn0); s0 += c[nt][0];
            c[nt][1] = ex2f(c[nt][1] - mn0); s0 += c[nt][1];
            c[nt][2] = ex2f(c[nt][2] - mn1); s1 += c[nt][2];
            c[nt][3] = ex2f(c[nt][3] - mn1); s1 += c[nt][3];
        }
        s0 += __shfl_xor_sync(0xffffffffu, s0, 1);
        s0 += __shfl_xor_sync(0xffffffffu, s0, 2);
        s1 += __shfl_xor_sync(0xffffffffu, s1, 1);
        s1 += __shfl_xor_sync(0xffffffffu, s1, 2);
        l0 = l0 * cor0 + s0; m0 = mn0;
        l1 = l1 * cor1 + s1; m1 = mn1;
#pragma unroll
        for (int i = 0; i < 16; i++) {
            O[i][0] *= cor0; O[i][1] *= cor0;
            O[i][2] *= cor1; O[i][3] *= cor1;
        }

        // ---- O += (Ph+Pl) Vh ----
        const uint32_t rxv = ((uint32_t)(lane & 7)) << 4;
        const uint32_t colb = (uint32_t)((lane >> 3) & 1) * 16;
#pragma unroll
        for (int kc2 = 0; kc2 < 2; kc2++) {
            uint32_t aph[4], apl[4];
            {
                float p00 = c[2 * kc2][0], p01 = c[2 * kc2][1];
                float p10 = c[2 * kc2][2], p11 = c[2 * kc2][3];
                float p20 = c[2 * kc2 + 1][0], p21 = c[2 * kc2 + 1][1];
                float p30 = c[2 * kc2 + 1][2], p31 = c[2 * kc2 + 1][3];
                aph[0] = packhf(p00, p01);
                aph[1] = packhf(p10, p11);
                aph[2] = packhf(p20, p21);
                aph[3] = packhf(p30, p31);
                __half2* t;
                t = (__half2*)&aph[0];
                apl[0] = packhf(p00 - __half2float(t->x), p01 - __half2float(t->y));
                t = (__half2*)&aph[1];
                apl[1] = packhf(p10 - __half2float(t->x), p11 - __half2float(t->y));
                t = (__half2*)&aph[2];
                apl[2] = packhf(p20 - __half2float(t->x), p21 - __half2float(t->y));
                t = (__half2*)&aph[3];
                apl[3] = packhf(p30 - __half2float(t->x), p31 - __half2float(t->y));
            }
            const uint32_t vrow = (uint32_t)(kc2 * 16 + (lane & 7) + (lane >> 4) * 8);
#pragma unroll
            for (int gg = 0; gg < 8; gg++) {
                uint32_t off = vrow * 256 + (((uint32_t)(gg * 32) + colb) ^ rxv);
                uint32_t vhf[4];
                ldm4t(vhf, sVH + off);
#pragma unroll
                for (int hf = 0; hf < 2; hf++) {
                    int nt2 = gg * 2 + hf;
                    mma16816h(O[nt2], aph, vhf[hf], vhf[hf + 2]);
                    mma16816h(O[nt2], apl, vhf[hf], vhf[hf + 2]);
                }
            }
        }
        __syncthreads();
    }

    // ---- Epilogue: normalize, split fp16 hi/lo, store y for proj GEMM ----
    const float il0 = 1.f / l0, il1 = 1.f / l1;
    const int row_lo = qb + wq0 + gro;
    size_t r0o = (size_t)(b * T_ + row_lo) * C_;
    size_t r1o = (size_t)(b * T_ + row_lo + 8) * C_;
#pragma unroll
    for (int nt2 = 0; nt2 < 16; nt2++) {
        int col = h * DH + nt2 * 8 + 2 * thr;
        float a0 = O[nt2][0] * il0, a1 = O[nt2][1] * il0;
        float b0 = O[nt2][2] * il1, b1 = O[nt2][3] * il1;
        uint32_t h0 = packhf(a0, a1);
        __half2 hv0 = *(__half2*)&h0;
        uint32_t l0w = packhf(a0 - __half2float(hv0.x), a1 - __half2float(hv0.y));
        uint32_t h1 = packhf(b0, b1);
        __half2 hv1 = *(__half2*)&h1;
        uint32_t l1w = packhf(b0 - __half2float(hv1.x), b1 - __half2float(hv1.y));
        *(uint32_t*)(yh + r0o + col) = h0;
        *(uint32_t*)(yl + r0o + col) = l0w;
        *(uint32_t*)(yh + r1o + col) = h1;
        *(uint32_t*)(yl + r1o + col) = l1w;
    }
}

// ---------------------------------------------------------------------------
// Launch
// ---------------------------------------------------------------------------
extern "C" void kernel_launch(void* const* d_in, const int* in_sizes, int n_in,
                              void* d_out, int out_size)
{
    (void)in_sizes; (void)n_in; (void)out_size;
    const float* x      = (const float*)d_in[0];
    const float* w_qkv  = (const float*)d_in[1];
    const float* b_qkv  = (const float*)d_in[2];
    const float* w_proj = (const float*)d_in[3];
    const float* b_proj = (const float*)d_in[4];
    float* out = (float*)d_out;

    void *p_xh, *p_xl, *p_yh, *p_yl, *p_wqh, *p_wph;
    void *p_qh, *p_ql, *p_kh, *p_vh;
    cudaGetSymbolAddress(&p_xh, g_xc_h);
    cudaGetSymbolAddress(&p_xl, g_xc_l);
    cudaGetSymbolAddress(&p_yh, g_yc_h);
    cudaGetSymbolAddress(&p_yl, g_yc_l);
    cudaGetSymbolAddress(&p_wqh, g_wq_h);
    cudaGetSymbolAddress(&p_wph, g_wp_h);
    cudaGetSymbolAddress(&p_qh, g_qh);
    cudaGetSymbolAddress(&p_ql, g_ql);
    cudaGetSymbolAddress(&p_kh, g_kh);
    cudaGetSymbolAddress(&p_vh, g_vh);

    cudaFuncSetAttribute(gemm_qkv_rope,
                         cudaFuncAttributeMaxDynamicSharedMemorySize, GEMM_DSM);
    cudaFuncSetAttribute(gemm_proj,
                         cudaFuncAttributeMaxDynamicSharedMemorySize, GEMM_DSM);
    cudaFuncSetAttribute(attn_hmma4,
                         cudaFuncAttributeMaxDynamicSharedMemorySize, ATTN3_DSM);

    // 0) Weight transpose (hi only) and x split (hi/lo fp16)
    wconv_h<<<dim3(THREE_C / 32, C_ / 32), dim3(32, 8)>>>(
        w_qkv, (__half*)p_wqh, C_, THREE_C);
    wconv_h<<<dim3(C_ / 32, C_ / 32), dim3(32, 8)>>>(
        w_proj, (__half*)p_wph, C_, C_);
    {
        long n8 = (long)M_ * C_ / 8;
        convert_hilo_h<<<(int)((n8 + 255) / 256), 256>>>(
            x, (__half*)p_xh, (__half*)p_xl, n8);
    }

    // 1) QKV GEMM (2-term fp16) + bias + RoPE + scale + split
    gemm_qkv_rope<<<dim3(THREE_C / 128, M_ / 128), GEMM_THREADS, GEMM_DSM>>>(
        (const __half*)p_xh, (const __half*)p_xl, (const __half*)p_wqh,
        b_qkv,
        (__half*)p_qh, (__half*)p_ql, (__half*)p_kh, (__half*)p_vh);

    // 2) Causal flash attention (fp16 2-term, K/V hi-only) -> y fp16 hi/lo
    {
        dim3 grid(T_ / 64, H_, B_);
        attn_hmma4<<<grid, 128, ATTN3_DSM>>>(
            (const __half*)p_qh, (const __half*)p_ql,
            (const __half*)p_kh, (const __half*)p_vh,
            (__half*)p_yh, (__half*)p_yl);
    }

    // 3) out = y @ w_proj + b_proj (2-term fp16, fp32 out)
    gemm_proj<<<dim3(C_ / 128, M_ / 128), GEMM_THREADS, GEMM_DSM>>>(
        (const __half*)p_yh, (const __half*)p_yl, (const __half*)p_wph,
        b_proj, out, C_, C_);
}

// round 17
// speedup vs baseline: 3.5644x; 1.5056x over previous
#include <cuda_runtime.h>
#include <cuda_fp16.h>
#include <math.h>
#include <stdint.h>

// Problem constants
#define B_ 4
#define T_ 2048
#define C_ 2048
#define H_ 16
#define DH 128
#define THREE_C (3 * C_)
#define M_ (B_ * T_)   // 8192

// ---------------------------------------------------------------------------
// Device-global scratch (allocation-free)
// ---------------------------------------------------------------------------
__device__ __half g_xc[(size_t)M_ * C_];             // x fp16
__device__ __half g_yc[(size_t)M_ * C_];             // y fp16
__device__ __half g_wq[(size_t)THREE_C * C_];        // w_qkv^T [6144,2048] fp16
__device__ __half g_wp[(size_t)C_ * C_];             // w_proj^T [2048,2048] fp16
// Roped/scaled fp16 Q (hi/lo) and K,V (hi only), layout [M_][C_] (c=h*128+d)
__device__ __half g_qh[(size_t)M_ * C_];
__device__ __half g_ql[(size_t)M_ * C_];
__device__ __half g_kh[(size_t)M_ * C_];
__device__ __half g_vh[(size_t)M_ * C_];

// ---------------------------------------------------------------------------
// Helpers
// ---------------------------------------------------------------------------
__device__ __forceinline__ uint32_t smem_u32(const void* p) {
    uint32_t a;
    asm("{ .reg .u64 t; cvta.to.shared.u64 t, %1; cvt.u32.u64 %0, t; }"
        : "=r"(a) : "l"(p));
    return a;
}
static __device__ __forceinline__ uint32_t sw128(uint32_t x) {
    return x ^ ((x >> 3) & 0x70);
}
__device__ __forceinline__ void cpa16(uint32_t s, const void* g) {
    asm volatile("cp.async.cg.shared.global [%0], [%1], 16;" :: "r"(s), "l"(g));
}
#define CP_COMMIT() asm volatile("cp.async.commit_group;" ::: "memory")
#define CP_WAIT1()  asm volatile("cp.async.wait_group 1;" ::: "memory")
#define CP_WAIT0()  asm volatile("cp.async.wait_group 0;" ::: "memory")

__device__ __forceinline__ void ldm4(uint32_t* r, uint32_t addr) {
    asm volatile("ldmatrix.sync.aligned.m8n8.x4.shared.b16 {%0,%1,%2,%3}, [%4];"
                 : "=r"(r[0]), "=r"(r[1]), "=r"(r[2]), "=r"(r[3]) : "r"(addr));
}
__device__ __forceinline__ void ldm4t(uint32_t* r, uint32_t addr) {
    asm volatile("ldmatrix.sync.aligned.m8n8.x4.trans.shared.b16 {%0,%1,%2,%3}, [%4];"
                 : "=r"(r[0]), "=r"(r[1]), "=r"(r[2]), "=r"(r[3]) : "r"(addr));
}
__device__ __forceinline__ void mma16816h(float* d, const uint32_t* a,
                                          uint32_t b0, uint32_t b1) {
    asm volatile(
        "mma.sync.aligned.m16n8k16.row.col.f32.f16.f16.f32 "
        "{%0,%1,%2,%3}, {%4,%5,%6,%7}, {%8,%9}, {%0,%1,%2,%3};"
        : "+f"(d[0]), "+f"(d[1]), "+f"(d[2]), "+f"(d[3])
        : "r"(a[0]), "r"(a[1]), "r"(a[2]), "r"(a[3]), "r"(b0), "r"(b1));
}
__device__ __forceinline__ uint32_t packhf(float a, float b) {
    __half2 t = __floats2half2_rn(a, b);   // .x = a (low 16 bits)
    return *(uint32_t*)&t;
}
__device__ __forceinline__ float ex2f(float x) {
    float r;
    asm("ex2.approx.f32 %0, %1;" : "=f"(r) : "f"(x));
    return r;
}

// ---------------------------------------------------------------------------
// Elementwise fp32 -> fp16 cast. n8 = elements/8.
// ---------------------------------------------------------------------------
__global__ void convert_h(const float* __restrict__ X,
                          __half* __restrict__ Hh, long n8)
{
    long i = (long)blockIdx.x * blockDim.x + threadIdx.x;
    if (i >= n8) return;
    float4 a = ((const float4*)X)[i * 2 + 0];
    float4 b = ((const float4*)X)[i * 2 + 1];
    union { __half e[8]; uint4 u; } ph;
    ph.e[0] = __float2half(a.x); ph.e[1] = __float2half(a.y);
    ph.e[2] = __float2half(a.z); ph.e[3] = __float2half(a.w);
    ph.e[4] = __float2half(b.x); ph.e[5] = __float2half(b.y);
    ph.e[6] = __float2half(b.z); ph.e[7] = __float2half(b.w);
    ((uint4*)Hh)[i] = ph.u;
}

// ---------------------------------------------------------------------------
// Transpose: W[K,N] fp32 -> Th [N,K] fp16
// ---------------------------------------------------------------------------
__global__ void wconv_h(const float* __restrict__ W, __half* __restrict__ Th,
                        int K, int N)
{
    __shared__ float ts[32][33];
    int n0 = blockIdx.x * 32, k0 = blockIdx.y * 32;
    int tx = threadIdx.x, ty = threadIdx.y;
    for (int i = ty; i < 32; i += 8)
        ts[i][tx] = W[(size_t)(k0 + i) * N + n0 + tx];
    __syncthreads();
    for (int i = ty; i < 32; i += 8) {
        float v = ts[tx][i];
        Th[(size_t)(n0 + i) * K + k0 + tx] = __float2half(v);
    }
}

// ---------------------------------------------------------------------------
// GEMM: CTA 128x128, 512 threads (16 warps, 4x4), warp tile 32x32, BK=64,
// 3-stage cp.async. 1-term fp16: D = A * B. Stage = 32KB.
// ---------------------------------------------------------------------------
#define GEMM_THREADS 512
#define BKc 64
#define A_H_OFF 0
#define B_H_OFF 16384
#define STG_BYTES 32768
#define STAGES 3
#define GEMM_DSM (STAGES * STG_BYTES + 1024)

#define G3_MAINLOOP(K_)                                                        \
    const int nch = (K_) / BKc;                                                \
    auto load_stage = [&](int st, int k0) {                                    \
        uint32_t sbase = sb + st * STG_BYTES;                                  \
        _Pragma("unroll")                                                      \
        for (int rep = 0; rep < 2; rep++) {                                    \
            int i = tid + rep * GEMM_THREADS;                                  \
            int row = i >> 3, cc = i & 7;                                      \
            uint32_t so = sw128((uint32_t)(row * 128 + cc * 16));              \
            size_t ga = (size_t)(rowBase + row) * (K_) + k0 + cc * 8;          \
            size_t gb = (size_t)(colBase + row) * (K_) + k0 + cc * 8;          \
            cpa16(sbase + A_H_OFF + so, Ah + ga);                              \
            cpa16(sbase + B_H_OFF + so, Bh + gb);                              \
        }                                                                      \
    };                                                                         \
    load_stage(0, 0); CP_COMMIT();                                             \
    load_stage(1, BKc); CP_COMMIT();                                           \
    float acc[2][4][4];                                                        \
    _Pragma("unroll")                                                          \
    for (int mi = 0; mi < 2; mi++)                                             \
        _Pragma("unroll")                                                      \
        for (int ni = 0; ni < 4; ni++)                                         \
            _Pragma("unroll")                                                  \
            for (int e = 0; e < 4; e++) acc[mi][ni][e] = 0.f;                  \
    const int lrow = lane & 15;                                                \
    const int lchunk = (lane >> 4) * 16;                                       \
    for (int c = 0; c < nch; c++) {                                            \
        CP_WAIT1();                                                            \
        __syncthreads();                                                       \
        int cn = c + STAGES - 1;                                               \
        if (cn < nch) load_stage(cn % STAGES, cn * BKc);                       \
        CP_COMMIT();                                                           \
        const uint32_t sbase = sb + (c % STAGES) * STG_BYTES;                  \
        _Pragma("unroll")                                                      \
        for (int ks = 0; ks < 4; ks++) {                                       \
            const int kb = ks * 32 + lchunk;                                   \
            uint32_t bh[2][4];                                                 \
            _Pragma("unroll")                                                  \
            for (int g = 0; g < 2; g++) {                                      \
                uint32_t bo = sw128((uint32_t)((wn + g * 16 + lrow) * 128 + kb)); \
                ldm4(bh[g], sbase + B_H_OFF + bo);                             \
            }                                                                  \
            _Pragma("unroll")                                                  \
            for (int mi = 0; mi < 2; mi++) {                                   \
                uint32_t ah[4];                                                \
                uint32_t ao = sw128((uint32_t)((wm + mi * 16 + lrow) * 128 + kb)); \
                ldm4(ah, sbase + A_H_OFF + ao);                                \
                _Pragma("unroll")                                              \
                for (int ni = 0; ni < 4; ni++) {                               \
                    int g = ni >> 1, hf = ni & 1;                              \
                    mma16816h(acc[mi][ni], ah, bh[g][hf], bh[g][hf + 2]);      \
                }                                                              \
            }                                                                  \
        }                                                                      \
    }

// ---------------------------------------------------------------------------
// GEMM #1: out = x @ w_qkv + b_qkv (1-term fp16).
// Epilogue: bias, RoPE (q,k), q scale; q -> fp16 hi/lo; k,v -> fp16 hi only.
// ---------------------------------------------------------------------------
__global__ __launch_bounds__(GEMM_THREADS, 1)
void gemm_qkv_rope(const __half* __restrict__ Ah,
                   const __half* __restrict__ Bh,
                   const float* __restrict__ bias,
                   __half* __restrict__ qh, __half* __restrict__ ql,
                   __half* __restrict__ kh, __half* __restrict__ vh)
{
    extern __shared__ char dsm[];
    const uint32_t raw = smem_u32(dsm);
    const uint32_t sb = (raw + 1023u) & ~1023u;

    const int tid = threadIdx.x;
    const int wid = tid >> 5, lane = tid & 31;
    const int wm = (wid & 3) * 32;
    const int wn = (wid >> 2) * 32;
    const int rowBase = blockIdx.y * 128;
    const int colBase = blockIdx.x * 128;

    G3_MAINLOOP(C_)

    const float QSC = 0.08838834764831845f * 1.4426950408889634f;
    const int gro = lane >> 2, thr = lane & 3;
#pragma unroll
    for (int mi = 0; mi < 2; mi++) {
        int r0 = rowBase + wm + mi * 16 + gro;
        int t0 = r0 & (T_ - 1), t1 = (r0 + 8) & (T_ - 1);
#pragma unroll
        for (int ni = 0; ni < 4; ni++) {
            int cb = colBase + wn + ni * 8 + thr * 2;   // even
            int sel = cb >> 11;          // 0=q, 1=k, 2=v
            int jj = cb & 2047;
            float bx = bias[cb], by = bias[cb + 1];
            float v00 = acc[mi][ni][0] + bx, v01 = acc[mi][ni][1] + by;
            float v10 = acc[mi][ni][2] + bx, v11 = acc[mi][ni][3] + by;
            if (sel < 2) {
                float e = (float)jj * (1.0f / (float)C_);
                float invf = expf(-9.210340371976184f * e);
                float ang = (float)t0 * invf;
                float kq = rintf(ang * 0.15915494309189535f);
                float rr = fmaf(-kq, 6.28318548202514648f, ang);
                rr = fmaf(-kq, -1.7484556000744083e-7f, rr);
                float s, c;
                __sincosf(rr, &s, &c);
                float o0 = v00 * c - v01 * s;
                float o1 = v00 * s + v01 * c;
                v00 = o0; v01 = o1;
                ang = (float)t1 * invf;
                kq = rintf(ang * 0.15915494309189535f);
                rr = fmaf(-kq, 6.28318548202514648f, ang);
                rr = fmaf(-kq, -1.7484556000744083e-7f, rr);
                __sincosf(rr, &s, &c);
                o0 = v10 * c - v11 * s;
                o1 = v10 * s + v11 * c;
                v10 = o0; v11 = o1;
            }
            size_t i0 = (size_t)r0 * C_ + jj;
            size_t i1 = (size_t)(r0 + 8) * C_ + jj;
            if (sel == 0) {
                v00 *= QSC; v01 *= QSC; v10 *= QSC; v11 *= QSC;
                uint32_t h0 = packhf(v00, v01);
                __half2 hv0 = *(__half2*)&h0;
                uint32_t l0 = packhf(v00 - __half2float(hv0.x),
                                     v01 - __half2float(hv0.y));
                uint32_t h1 = packhf(v10, v11);
                __half2 hv1 = *(__half2*)&h1;
                uint32_t l1 = packhf(v10 - __half2float(hv1.x),
                                     v11 - __half2float(hv1.y));
                *(uint32_t*)(qh + i0) = h0;
                *(uint32_t*)(ql + i0) = l0;
                *(uint32_t*)(qh + i1) = h1;
                *(uint32_t*)(ql + i1) = l1;
            } else {
                __half* dst = (sel == 1) ? kh : vh;
                *(uint32_t*)(dst + i0) = packhf(v00, v01);
                *(uint32_t*)(dst + i1) = packhf(v10, v11);
            }
        }
    }
}

// ---------------------------------------------------------------------------
// GEMM #2: out = y @ w_proj + b_proj (fp32 out), 1-term fp16.
// ---------------------------------------------------------------------------
__global__ __launch_bounds__(GEMM_THREADS, 1)
void gemm_proj(const __half* __restrict__ Ah,
               const __half* __restrict__ Bh,
               const float* __restrict__ bias, float* __restrict__ Cm,
               int N, int K)
{
    extern __shared__ char dsm[];
    const uint32_t raw = smem_u32(dsm);
    const uint32_t sb = (raw + 1023u) & ~1023u;

    const int tid = threadIdx.x;
    const int wid = tid >> 5, lane = tid & 31;
    const int wm = (wid & 3) * 32;
    const int wn = (wid >> 2) * 32;
    const int rowBase = blockIdx.y * 128;
    const int colBase = blockIdx.x * 128;

    G3_MAINLOOP(K)

    const int gro = lane >> 2, thr = lane & 3;
#pragma unroll
    for (int mi = 0; mi < 2; mi++) {
        int r0 = rowBase + wm + mi * 16 + gro;
#pragma unroll
        for (int ni = 0; ni < 4; ni++) {
            int cb = colBase + wn + ni * 8 + thr * 2;
            float bx = bias[cb], by = bias[cb + 1];
            float2 o0, o1;
            o0.x = acc[mi][ni][0] + bx; o0.y = acc[mi][ni][1] + by;
            o1.x = acc[mi][ni][2] + bx; o1.y = acc[mi][ni][3] + by;
            *(float2*)(Cm + (size_t)r0 * N + cb) = o0;
            *(float2*)(Cm + (size_t)(r0 + 8) * N + cb) = o1;
        }
    }
}

// ---------------------------------------------------------------------------
// fp16 flash attention (unchanged from R16-passing version except y output
// is hi only): S = (Qh+Ql)*Kh, O += (Ph+Pl)*Vh. 64 q-rows/CTA, 4 warps,
// Q in regs, 32-row KV tiles double-buffered via cp.async, 2 CTAs/SM.
// ---------------------------------------------------------------------------
#define QSTG 0
#define QSTG_L 16384
#define KV0 32768
#define KVSTB 16384
#define KH_O 0
#define VH_O 8192
#define ATTN3_DSM (32768 + 2 * 16384 + 1024)

__global__ __launch_bounds__(128, 2)
void attn_hmma4(const __half* __restrict__ qh, const __half* __restrict__ ql,
                const __half* __restrict__ kh, const __half* __restrict__ vh,
                __half* __restrict__ yh)
{
    extern __shared__ char asmem[];
    const uint32_t raw = smem_u32(asmem);
    const uint32_t sb = (raw + 1023u) & ~1023u;

    const int qt = blockIdx.x, h = blockIdx.y, b = blockIdx.z;
    const int qb = qt * 64;
    const int tid = threadIdx.x;
    const int wid = tid >> 5, lane = tid & 31;
    const int wq0 = wid * 16;
    const int lrow = lane & 15;
    const int lch = (lane >> 4) * 16;
    const int gro = lane >> 2, thr = lane & 3;
    const uint32_t rx = ((uint32_t)(lrow & 7)) << 4;

#pragma unroll
    for (int rep = 0; rep < 8; rep++) {
        int idx = tid + rep * 128;
        int row = idx >> 4, ch = idx & 15;
        uint32_t so = (uint32_t)row * 256 +
                      (((uint32_t)(ch * 16)) ^ (((uint32_t)(row & 7)) << 4));
        size_t g = ((size_t)(b * T_ + qb + row)) * C_ + h * DH + ch * 8;
        cpa16(sb + QSTG + so, qh + g);
        cpa16(sb + QSTG_L + so, ql + g);
    }
    CP_COMMIT();

    auto loadKV = [&](int st, int j2) {
        uint32_t stb = sb + KV0 + st * KVSTB;
        size_t grow = ((size_t)(b * T_ + j2 * 32)) * C_ + h * DH;
#pragma unroll
        for (int rep = 0; rep < 4; rep++) {
            int idx = tid + rep * 128;
            int row = idx >> 4, ch = idx & 15;
            uint32_t so = (uint32_t)row * 256 +
                          (((uint32_t)(ch * 16)) ^ (((uint32_t)(row & 7)) << 4));
            size_t g = grow + (size_t)row * C_ + ch * 8;
            cpa16(stb + KH_O + so, kh + g);
            cpa16(stb + VH_O + so, vh + g);
        }
    };

    loadKV(0, 0);
    CP_COMMIT();

    CP_WAIT1();
    __syncthreads();
    uint32_t aqh[8][4], aql[8][4];
#pragma unroll
    for (int kc = 0; kc < 8; kc++) {
        uint32_t off = (uint32_t)(wq0 + lrow) * 256 +
                       (((uint32_t)(kc * 32 + lch)) ^ rx);
        ldm4(aqh[kc], sb + QSTG + off);
        ldm4(aql[kc], sb + QSTG_L + off);
    }

    float m0 = -INFINITY, m1 = -INFINITY, l0 = 0.f, l1 = 0.f;
    float O[16][4];
#pragma unroll
    for (int i = 0; i < 16; i++)
#pragma unroll
        for (int e = 0; e < 4; e++) O[i][e] = 0.f;

    const int ntiles = 2 * qt + 2;
    for (int j = 0; j < ntiles; j++) {
        const int kvg = j * 32;
        if (j + 1 < ntiles) {
            loadKV((j + 1) & 1, j + 1);
            CP_COMMIT();
            CP_WAIT1();
        } else {
            CP_WAIT0();
        }
        __syncthreads();

        const uint32_t stb = sb + KV0 + (j & 1) * KVSTB;
        const uint32_t sKH = stb + KH_O;
        const uint32_t sVH = stb + VH_O;

        float c[4][4];
#pragma unroll
        for (int nt = 0; nt < 4; nt++)
#pragma unroll
            for (int e = 0; e < 4; e++) c[nt][e] = 0.f;

#pragma unroll
        for (int kc = 0; kc < 8; kc++) {
            const uint32_t kb = (uint32_t)(kc * 32 + lch);
#pragma unroll
            for (int g4 = 0; g4 < 2; g4++) {
                uint32_t off = (uint32_t)(g4 * 16 + lrow) * 256 + (kb ^ rx);
                uint32_t bh[4];
                ldm4(bh, sKH + off);
#pragma unroll
                for (int hf = 0; hf < 2; hf++) {
                    int nt = g4 * 2 + hf;
                    mma16816h(c[nt], aqh[kc], bh[hf], bh[hf + 2]);
                    mma16816h(c[nt], aql[kc], bh[hf], bh[hf + 2]);
                }
            }
        }

        const int row_lo = qb + wq0 + gro;
        const int row_hi = row_lo + 8;
        if (kvg + 31 > qb + wq0) {
#pragma unroll
            for (int nt = 0; nt < 4; nt++) {
                int cbase = kvg + nt * 8 + 2 * thr;
                if (cbase > row_lo)     c[nt][0] = -1e30f;
                if (cbase + 1 > row_lo) c[nt][1] = -1e30f;
                if (cbase > row_hi)     c[nt][2] = -1e30f;
                if (cbase + 1 > row_hi) c[nt][3] = -1e30f;
            }
        }

        float mt0 = -1e30f, mt1 = -1e30f;
#pragma unroll
        for (int nt = 0; nt < 4; nt++) {
            mt0 = fmaxf(mt0, fmaxf(c[nt][0], c[nt][1]));
            mt1 = fmaxf(mt1, fmaxf(c[nt][2], c[nt][3]));
        }
        mt0 = fmaxf(mt0, __shfl_xor_sync(0xffffffffu, mt0, 1));
        mt0 = fmaxf(mt0, __shfl_xor_sync(0xffffffffu, mt0, 2));
        mt1 = fmaxf(mt1, __shfl_xor_sync(0xffffffffu, mt1, 1));
        mt1 = fmaxf(mt1, __shfl_xor_sync(0xffffffffu, mt1, 2));
        float mn0 = fmaxf(m0, mt0), mn1 = fmaxf(m1, mt1);
        float cor0 = ex2f(m0 - mn0), cor1 = ex2f(m1 - mn1);
        float s0 = 0.f, s1 = 0.f;
#pragma unroll
        for (int nt = 0; nt < 4; nt++) {
            c[nt][0] = ex2f(c[nt][0] - mn0); s0 += c[nt][0];
            c[nt][1] = ex2f(c[nt][1] - mn0); s0 += c[nt][1];
            c[nt][2] = ex2f(c[nt][2] - mn1); s1 += c[nt][2];
            c[nt][3] = ex2f(c[nt][3] - mn1); s1 += c[nt][3];
        }
        s0 += __shfl_xor_sync(0xffffffffu, s0, 1);
        s0 += __shfl_xor_sync(0xffffffffu, s0, 2);
        s1 += __shfl_xor_sync(0xffffffffu, s1, 1);
        s1 += __shfl_xor_sync(0xffffffffu, s1, 2);
        l0 = l0 * cor0 + s0; m0 = mn0;
        l1 = l1 * cor1 + s1; m1 = mn1;
#pragma unroll
        for (int i = 0; i < 16; i++) {
            O[i][0] *= cor0; O[i][1] *= cor0;
            O[i][2] *= cor1; O[i][3] *= cor1;
        }

        const uint32_t rxv = ((uint32_t)(lane & 7)) << 4;
        const uint32_t colb = (uint32_t)((lane >> 3) & 1) * 16;
#pragma unroll
        for (int kc2 = 0; kc2 < 2; kc2++) {
            uint32_t aph[4], apl[4];
            {
                float p00 = c[2 * kc2][0], p01 = c[2 * kc2][1];
                float p10 = c[2 * kc2][2], p11 = c[2 * kc2][3];
                float p20 = c[2 * kc2 + 1][0], p21 = c[2 * kc2 + 1][1];
                float p30 = c[2 * kc2 + 1][2], p31 = c[2 * kc2 + 1][3];
                aph[0] = packhf(p00, p01);
                aph[1] = packhf(p10, p11);
                aph[2] = packhf(p20, p21);
                aph[3] = packhf(p30, p31);
                __half2* t;
                t = (__half2*)&aph[0];
                apl[0] = packhf(p00 - __half2float(t->x), p01 - __half2float(t->y));
                t = (__half2*)&aph[1];
                apl[1] = packhf(p10 - __half2float(t->x), p11 - __half2float(t->y));
                t = (__half2*)&aph[2];
                apl[2] = packhf(p20 - __half2float(t->x), p21 - __half2float(t->y));
                t = (__half2*)&aph[3];
                apl[3] = packhf(p30 - __half2float(t->x), p31 - __half2float(t->y));
            }
            const uint32_t vrow = (uint32_t)(kc2 * 16 + (lane & 7) + (lane >> 4) * 8);
#pragma unroll
            for (int gg = 0; gg < 8; gg++) {
                uint32_t off = vrow * 256 + (((uint32_t)(gg * 32) + colb) ^ rxv);
                uint32_t vhf[4];
                ldm4t(vhf, sVH + off);
#pragma unroll
                for (int hf = 0; hf < 2; hf++) {
                    int nt2 = gg * 2 + hf;
                    mma16816h(O[nt2], aph, vhf[hf], vhf[hf + 2]);
                    mma16816h(O[nt2], apl, vhf[hf], vhf[hf + 2]);
                }
            }
        }
        __syncthreads();
    }

    // ---- Epilogue: normalize, store y fp16 (hi only) for proj GEMM ----
    const float il0 = 1.f / l0, il1 = 1.f / l1;
    const int row_lo = qb + wq0 + gro;
    size_t r0o = (size_t)(b * T_ + row_lo) * C_;
    size_t r1o = (size_t)(b * T_ + row_lo + 8) * C_;
#pragma unroll
    for (int nt2 = 0; nt2 < 16; nt2++) {
        int col = h * DH + nt2 * 8 + 2 * thr;
        *(uint32_t*)(yh + r0o + col) = packhf(O[nt2][0] * il0, O[nt2][1] * il0);
        *(uint32_t*)(yh + r1o + col) = packhf(O[nt2][2] * il1, O[nt2][3] * il1);
    }
}

// ---------------------------------------------------------------------------
// Launch
// ---------------------------------------------------------------------------
extern "C" void kernel_launch(void* const* d_in, const int* in_sizes, int n_in,
                              void* d_out, int out_size)
{
    (void)in_sizes; (void)n_in; (void)out_size;
    const float* x      = (const float*)d_in[0];
    const float* w_qkv  = (const float*)d_in[1];
    const float* b_qkv  = (const float*)d_in[2];
    const float* w_proj = (const float*)d_in[3];
    const float* b_proj = (const float*)d_in[4];
    float* out = (float*)d_out;

    void *p_x, *p_y, *p_wq, *p_wp, *p_qh, *p_ql, *p_kh, *p_vh;
    cudaGetSymbolAddress(&p_x, g_xc);
    cudaGetSymbolAddress(&p_y, g_yc);
    cudaGetSymbolAddress(&p_wq, g_wq);
    cudaGetSymbolAddress(&p_wp, g_wp);
    cudaGetSymbolAddress(&p_qh, g_qh);
    cudaGetSymbolAddress(&p_ql, g_ql);
    cudaGetSymbolAddress(&p_kh, g_kh);
    cudaGetSymbolAddress(&p_vh, g_vh);

    cudaFuncSetAttribute(gemm_qkv_rope,
                         cudaFuncAttributeMaxDynamicSharedMemorySize, GEMM_DSM);
    cudaFuncSetAttribute(gemm_proj,
                         cudaFuncAttributeMaxDynamicSharedMemorySize, GEMM_DSM);
    cudaFuncSetAttribute(attn_hmma4,
                         cudaFuncAttributeMaxDynamicSharedMemorySize, ATTN3_DSM);

    // 0) Weight transpose (fp16) and x cast (fp16)
    wconv_h<<<dim3(THREE_C / 32, C_ / 32), dim3(32, 8)>>>(
        w_qkv, (__half*)p_wq, C_, THREE_C);
    wconv_h<<<dim3(C_ / 32, C_ / 32), dim3(32, 8)>>>(
        w_proj, (__half*)p_wp, C_, C_);
    {
        long n8 = (long)M_ * C_ / 8;
        convert_h<<<(int)((n8 + 255) / 256), 256>>>(x, (__half*)p_x, n8);
    }

    // 1) QKV GEMM (1-term fp16) + bias + RoPE + scale + split
    gemm_qkv_rope<<<dim3(THREE_C / 128, M_ / 128), GEMM_THREADS, GEMM_DSM>>>(
        (const __half*)p_x, (const __half*)p_wq, b_qkv,
        (__half*)p_qh, (__half*)p_ql, (__half*)p_kh, (__half*)p_vh);

    // 2) Causal flash attention (fp16, Q 2-term) -> y fp16
    {
        dim3 grid(T_ / 64, H_, B_);
        attn_hmma4<<<grid, 128, ATTN3_DSM>>>(
            (const __half*)p_qh, (const __half*)p_ql,
            (const __half*)p_kh, (const __half*)p_vh,
            (__half*)p_y);
    }

    // 3) out = y @ w_proj + b_proj (1-term fp16, fp32 out)
    gemm_proj<<<dim3(C_ / 128, M_ / 128), GEMM_THREADS, GEMM_DSM>>>(
        (const __half*)p_y, (const __half*)p_wp, b_proj, out, C_, C_);
}